// round 3
// baseline (speedup 1.0000x reference)
#include <cuda_runtime.h>
#include <math.h>

#define TB 256

// Problem sizes
#define Bn   1024
#define DIMn 384
#define HIDn 64
#define Kn   8
#define Gn   48
#define MIDn 128

// Shared-memory layout (in floats)
#define HW_STRIDE 514                       // 512 used + 2 pad (bank stagger for float2)
#define S_H   0                             // H: 384 x 64                  (24576)
#define S_U   24576                         // union region                 (26976)
#define S_HW  (S_U)                         // Hw: 48 x 514                 (24672)
#define S_PG  (S_U + 24672)                 // Pg: 48 x 48                  (2304)
// Stage-E overlays of the union region:
#define S_DWT (S_U)                         // down_w^T: [h][m] 64 x 132    (8448)
#define S_UWT (S_U + 8448)                  // up_w^T:   [m][n] 128 x 68    (8704)
#define S_Z   (S_U + 8448 + 8704)           // z chunk:  [r][m] 64 x 132    (8448)
#define S_X   (S_U + 26976)                 // x row: 384
#define S_INV (S_X + 384)                   // 1/(|x|+eps): 384
#define S_SW  (S_INV + 384)                 // softmaxed patch weight: 64
#define S_SC  (S_SW + 64)                   // scales: 384
#define S_RW  (S_SC + 384)                  // row_weights: 48
#define S_DB  (S_RW + 48)                   // down_b: 128
#define S_UB  (S_DB + 128)                  // up_b: 64
#define SMEM_FLOATS (S_UB + 64)             // 53008 floats = 212032 bytes

__device__ __forceinline__ float leaky(float v) {
    return (v >= 0.0f) ? v : 0.01f * v;
}

__device__ __forceinline__ float gelu_exact(float v) {
    return 0.5f * v * (1.0f + erff(v * 0.70710678118654752f));
}

__global__ void __launch_bounds__(TB, 1) autoreg_fused_kernel(
    const float* __restrict__ x,
    const float* __restrict__ W,
    const float* __restrict__ bia,
    const float* __restrict__ patchw,
    const float* __restrict__ pw1,
    const float* __restrict__ pb1,
    const float* __restrict__ pw2,
    const float* __restrict__ pb2,
    const float* __restrict__ projw,
    const float* __restrict__ projb,
    const float* __restrict__ dw,
    const float* __restrict__ db,
    const float* __restrict__ uw,
    const float* __restrict__ ub,
    float* __restrict__ out)
{
    extern __shared__ float sm[];
    const int tid  = threadIdx.x;
    const int bidx = blockIdx.x;

    // ---- Load x row, bias vectors, raw patch weights ----
    for (int i = tid; i < DIMn; i += TB) {
        float xv = x[bidx * DIMn + i];
        sm[S_X + i]   = xv;
        sm[S_INV + i] = 1.0f / (fabsf(xv) + 1e-6f);
    }
    for (int i = tid; i < MIDn; i += TB) sm[S_DB + i] = db[i];
    for (int i = tid; i < HIDn; i += TB) sm[S_UB + i] = ub[i];
    if (tid < 64) sm[S_SW + tid] = patchw[tid];
    __syncthreads();

    // ---- Patch-weight softmax (tiny; thread 0, overlapped with stage A of others) ----
    if (tid == 0) {
        float m = -1e30f;
        for (int i = 0; i < 64; i++) m = fmaxf(m, sm[S_SW + i]);
        float s = 0.0f;
        for (int i = 0; i < 64; i++) { float e = expf(sm[S_SW + i] - m); sm[S_SW + i] = e; s += e; }
        float is = 1.0f / s;
        for (int i = 0; i < 64; i++) sm[S_SW + i] *= is;
    }

    // ---- Stage A: H[i,c] = gelu(x_i*W[i,c] + inv_i*b[i,c]) ----
    for (int t = tid; t < DIMn * HIDn; t += TB) {
        int i = t >> 6;
        float v = sm[S_X + i] * W[t] + sm[S_INV + i] * bia[t];
        sm[S_H + t] = gelu_exact(v);
    }
    __syncthreads();

    // ---- Stage B: Hw[h,k,c] = sum_l w[k,l] * H[h*8+l, c] ----
    for (int p = tid; p < Gn * HIDn; p += TB) {       // 3072 (h,c) pairs
        int h = p >> 6, c = p & 63;
        float hv[8];
        #pragma unroll
        for (int l = 0; l < 8; l++) hv[l] = sm[S_H + (h * 8 + l) * 64 + c];
        #pragma unroll
        for (int k = 0; k < 8; k++) {
            float acc = 0.0f;
            #pragma unroll
            for (int l = 0; l < 8; l++) acc = fmaf(sm[S_SW + k * 8 + l], hv[l], acc);
            sm[S_HW + h * HW_STRIDE + k * 64 + c] = acc;
        }
    }
    __syncthreads();

    // ---- Stage C: Pg[g,h] = sum_{kc<512} H[g,kc] * Hw[h,kc]  (48x48x512 GEMM) ----
    {
        const int tg = tid >> 4;            // 0..15 -> 3 g rows
        const int th = tid & 15;            // 0..15 -> 3 h rows
        const int g0 = tg * 3, h0 = th * 3;
        float acc[3][3];
        #pragma unroll
        for (int a = 0; a < 3; a++)
            #pragma unroll
            for (int b2 = 0; b2 < 3; b2++) acc[a][b2] = 0.0f;

        const float2* H2  = (const float2*)&sm[S_H];
        const float2* HW2 = (const float2*)&sm[S_HW];
        #pragma unroll 4
        for (int kc2 = 0; kc2 < 256; kc2++) {
            float2 a0 = H2[(g0 + 0) * 256 + kc2];
            float2 a1 = H2[(g0 + 1) * 256 + kc2];
            float2 a2 = H2[(g0 + 2) * 256 + kc2];
            float2 b0 = HW2[(h0 + 0) * 257 + kc2];
            float2 b1 = HW2[(h0 + 1) * 257 + kc2];
            float2 b2 = HW2[(h0 + 2) * 257 + kc2];
            acc[0][0] = fmaf(a0.x, b0.x, fmaf(a0.y, b0.y, acc[0][0]));
            acc[0][1] = fmaf(a0.x, b1.x, fmaf(a0.y, b1.y, acc[0][1]));
            acc[0][2] = fmaf(a0.x, b2.x, fmaf(a0.y, b2.y, acc[0][2]));
            acc[1][0] = fmaf(a1.x, b0.x, fmaf(a1.y, b0.y, acc[1][0]));
            acc[1][1] = fmaf(a1.x, b1.x, fmaf(a1.y, b1.y, acc[1][1]));
            acc[1][2] = fmaf(a1.x, b2.x, fmaf(a1.y, b2.y, acc[1][2]));
            acc[2][0] = fmaf(a2.x, b0.x, fmaf(a2.y, b0.y, acc[2][0]));
            acc[2][1] = fmaf(a2.x, b1.x, fmaf(a2.y, b1.y, acc[2][1]));
            acc[2][2] = fmaf(a2.x, b2.x, fmaf(a2.y, b2.y, acc[2][2]));
        }
        #pragma unroll
        for (int a = 0; a < 3; a++)
            #pragma unroll
            for (int b2 = 0; b2 < 3; b2++)
                sm[S_PG + (g0 + a) * 48 + (h0 + b2)] = acc[a][b2];
    }
    __syncthreads();

    // ---- Stage D: elementwise affines + leaky ----
    for (int t = tid; t < Gn * Gn; t += TB) {
        float v = sm[S_PG + t];
        v = leaky(fmaf(v, pw1[t], pb1[t]));
        v = leaky(fmaf(v, pw2[t], pb2[t]));
        sm[S_PG + t] = v;
    }
    __syncthreads();

    // ---- Row softmax + row_weights ----
    if (tid < Gn) {
        const float* row = &sm[S_PG + tid * 48];
        float m = -1e30f;
        for (int h = 0; h < 48; h++) m = fmaxf(m, row[h]);
        float s = 0.0f;
        for (int h = 0; h < 48; h++) s += expf(row[h] - m);
        float inv_s = 1.0f / s;
        float rw = 0.0f;
        for (int h = 0; h < 48; h++) {
            float p = expf(row[h] - m) * inv_s;
            rw += 1.0f / (1.0f + p * p);
        }
        sm[S_RW + tid] = rw;
    }
    __syncthreads();

    // ---- scales[i] = row_weights . proj_w[i,:] + proj_b[i] ----
    for (int i = tid; i < DIMn; i += TB) {
        float acc = projb[i];
        const float* pr = &projw[i * Gn];
        #pragma unroll
        for (int g = 0; g < Gn; g++) acc = fmaf(sm[S_RW + g], pr[g], acc);
        sm[S_SC + i] = acc;
    }
    __syncthreads();

    // ---- Scale H in place; load transposed down_w / up_w into the freed union region ----
    for (int t = tid; t < DIMn * HIDn; t += TB) sm[S_H + t] *= sm[S_SC + (t >> 6)];
    for (int t = tid; t < MIDn * HIDn; t += TB) {       // down_w (128,64) -> [h][m]
        int m = t >> 6, h = t & 63;
        sm[S_DWT + h * 132 + m] = dw[t];
    }
    for (int t = tid; t < HIDn * MIDn; t += TB) {       // up_w (64,128) -> [m][n]
        int m = t >> 6, n = t & 63;
        sm[S_UWT + m * 68 + n] = uw[n * MIDn + m];
    }
    __syncthreads();

    // ---- Stage E: per 64-row chunk: z = leaky(H @ dw^T + db); out = leaky(z @ uw^T + ub) ----
    const int tr = tid >> 4;         // 0..15 -> 4 rows each
    const int tm = tid & 15;         // 0..15 -> cols {4tm..4tm+3, 64+4tm..64+4tm+3} / n0=4tm
    const int tr4 = tr * 4;

    for (int ch = 0; ch < 6; ch++) {
        const int r0 = ch * 64;

        // GEMM1: 64x128, K=64
        float acc[4][8];
        #pragma unroll
        for (int j = 0; j < 4; j++)
            #pragma unroll
            for (int q = 0; q < 8; q++) acc[j][q] = 0.0f;

        #pragma unroll 4
        for (int h = 0; h < HIDn; h++) {
            float4 bA = *(const float4*)&sm[S_DWT + h * 132 + 4 * tm];
            float4 bB = *(const float4*)&sm[S_DWT + h * 132 + 64 + 4 * tm];
            #pragma unroll
            for (int j = 0; j < 4; j++) {
                float av = sm[S_H + (r0 + tr4 + j) * 64 + h];
                acc[j][0] = fmaf(av, bA.x, acc[j][0]);
                acc[j][1] = fmaf(av, bA.y, acc[j][1]);
                acc[j][2] = fmaf(av, bA.z, acc[j][2]);
                acc[j][3] = fmaf(av, bA.w, acc[j][3]);
                acc[j][4] = fmaf(av, bB.x, acc[j][4]);
                acc[j][5] = fmaf(av, bB.y, acc[j][5]);
                acc[j][6] = fmaf(av, bB.z, acc[j][6]);
                acc[j][7] = fmaf(av, bB.w, acc[j][7]);
            }
        }
        #pragma unroll
        for (int j = 0; j < 4; j++) {
            float4 vA, vB;
            vA.x = leaky(acc[j][0] + sm[S_DB + 4 * tm + 0]);
            vA.y = leaky(acc[j][1] + sm[S_DB + 4 * tm + 1]);
            vA.z = leaky(acc[j][2] + sm[S_DB + 4 * tm + 2]);
            vA.w = leaky(acc[j][3] + sm[S_DB + 4 * tm + 3]);
            vB.x = leaky(acc[j][4] + sm[S_DB + 64 + 4 * tm + 0]);
            vB.y = leaky(acc[j][5] + sm[S_DB + 64 + 4 * tm + 1]);
            vB.z = leaky(acc[j][6] + sm[S_DB + 64 + 4 * tm + 2]);
            vB.w = leaky(acc[j][7] + sm[S_DB + 64 + 4 * tm + 3]);
            *(float4*)&sm[S_Z + (tr4 + j) * 132 + 4 * tm] = vA;
            *(float4*)&sm[S_Z + (tr4 + j) * 132 + 64 + 4 * tm] = vB;
        }
        __syncthreads();

        // GEMM2: 64x64, K=128
        float acc2[4][4];
        #pragma unroll
        for (int j = 0; j < 4; j++)
            #pragma unroll
            for (int q = 0; q < 4; q++) acc2[j][q] = 0.0f;

        #pragma unroll 4
        for (int m = 0; m < MIDn; m++) {
            float4 bv = *(const float4*)&sm[S_UWT + m * 68 + 4 * tm];
            #pragma unroll
            for (int j = 0; j < 4; j++) {
                float av = sm[S_Z + (tr4 + j) * 132 + m];
                acc2[j][0] = fmaf(av, bv.x, acc2[j][0]);
                acc2[j][1] = fmaf(av, bv.y, acc2[j][1]);
                acc2[j][2] = fmaf(av, bv.z, acc2[j][2]);
                acc2[j][3] = fmaf(av, bv.w, acc2[j][3]);
            }
        }
        #pragma unroll
        for (int j = 0; j < 4; j++) {
            float4 o;
            o.x = leaky(acc2[j][0] + sm[S_UB + 4 * tm + 0]);
            o.y = leaky(acc2[j][1] + sm[S_UB + 4 * tm + 1]);
            o.z = leaky(acc2[j][2] + sm[S_UB + 4 * tm + 2]);
            o.w = leaky(acc2[j][3] + sm[S_UB + 4 * tm + 3]);
            *(float4*)&out[((size_t)(bidx * DIMn + r0 + tr4 + j)) * 64 + 4 * tm] = o;
        }
        __syncthreads();
    }
}

extern "C" void kernel_launch(void* const* d_in, const int* in_sizes, int n_in,
                              void* d_out, int out_size) {
    (void)in_sizes; (void)n_in; (void)out_size;
    const float* x      = (const float*)d_in[0];
    const float* W      = (const float*)d_in[1];
    const float* bia    = (const float*)d_in[2];
    const float* patchw = (const float*)d_in[3];
    const float* pw1    = (const float*)d_in[4];
    const float* pb1    = (const float*)d_in[5];
    const float* pw2    = (const float*)d_in[6];
    const float* pb2    = (const float*)d_in[7];
    const float* projw  = (const float*)d_in[8];
    const float* projb  = (const float*)d_in[9];
    const float* dw     = (const float*)d_in[10];
    const float* db     = (const float*)d_in[11];
    const float* uw     = (const float*)d_in[12];
    const float* ub     = (const float*)d_in[13];
    float* out = (float*)d_out;

    cudaFuncSetAttribute(autoreg_fused_kernel,
                         cudaFuncAttributeMaxDynamicSharedMemorySize,
                         SMEM_FLOATS * sizeof(float));
    autoreg_fused_kernel<<<Bn, TB, SMEM_FLOATS * sizeof(float)>>>(
        x, W, bia, patchw, pw1, pb1, pw2, pb2, projw, projb, dw, db, uw, ub, out);
}

// round 5
// speedup vs baseline: 1.4876x; 1.4876x over previous
#include <cuda_runtime.h>
#include <cuda_bf16.h>
#include <math.h>
#include <stdint.h>

#define TB 256

// Problem sizes
#define Bn   1024
#define DIMn 384
#define HIDn 64
#define Gn   48
#define MIDn 128

// ---------------- Shared-memory layout (float indices) ----------------
#define HW_STRIDE 514
#define S_H   0                             // H: 384 x 64 fp32 (bytes 0..98303)
#define S_U   24576                         // union region (bytes 98304..206207)
#define S_HW  (S_U)                         // Hw: 48 x 514 (stages B-C)
#define S_PG  (S_U + 24672)                 // Pg: 48 x 48   (stages C-D)
#define S_X   (S_U + 26976)
#define S_INV (S_X + 384)
#define S_SW  (S_INV + 384)
#define S_SC  (S_SW + 64)
#define S_RW  (S_SC + 384)
#define S_DB  (S_RW + 48)
#define S_UB  (S_DB + 128)
#define SMEM_FLOATS (S_UB + 64)             // 53008 floats = 212032 bytes

// Stage-E overlays (byte offsets from smem base):
//  A-split: union region, 384 rows x 272B ([128B hi][128B lo][16B pad])   98304..202751
//  z double buffers: H region, 2 x (32 rows x 528B = [256 hi][256 lo][16 pad])  0..33791
#define EB_AS   98304
#define AS_STRIDE 272
#define EB_Z    0
#define Z_STRIDE 528
#define Z_BUFSZ 16896

// ---------------- mma.sync / ldmatrix helpers (sm_80+ features only) ----------------
__device__ __forceinline__ uint32_t smem_u32(const void* p) {
    uint32_t a;
    asm("{ .reg .u64 t; cvta.to.shared.u64 t, %1; cvt.u32.u64 %0, t; }" : "=r"(a) : "l"(p));
    return a;
}
__device__ __forceinline__ void mma_bf16(float* d, const uint32_t* a, const uint32_t* b) {
    asm volatile("mma.sync.aligned.m16n8k16.row.col.f32.bf16.bf16.f32 "
        "{%0,%1,%2,%3}, {%4,%5,%6,%7}, {%8,%9}, {%0,%1,%2,%3};"
        : "+f"(d[0]), "+f"(d[1]), "+f"(d[2]), "+f"(d[3])
        : "r"(a[0]), "r"(a[1]), "r"(a[2]), "r"(a[3]), "r"(b[0]), "r"(b[1]));
}
__device__ __forceinline__ void ldsm_x4(uint32_t* r, uint32_t addr) {
    asm volatile("ldmatrix.sync.aligned.m8n8.x4.shared.b16 {%0,%1,%2,%3}, [%4];"
        : "=r"(r[0]), "=r"(r[1]), "=r"(r[2]), "=r"(r[3]) : "r"(addr));
}

__device__ __forceinline__ float leaky(float v) { return (v >= 0.0f) ? v : 0.01f * v; }
__device__ __forceinline__ float gelu_exact(float v) {
    return 0.5f * v * (1.0f + erff(v * 0.70710678118654752f));
}
__device__ __forceinline__ uint32_t bf2(float a, float b) {
    __nv_bfloat162 t; t.x = __float2bfloat16(a); t.y = __float2bfloat16(b);
    return *reinterpret_cast<uint32_t*>(&t);
}
// hi/lo split of a float pair into two packed bf16x2 words (a -> low half)
__device__ __forceinline__ void split2(float a, float b, uint32_t &hi, uint32_t &lo) {
    __nv_bfloat16 ha = __float2bfloat16(a);
    __nv_bfloat16 hb = __float2bfloat16(b);
    __nv_bfloat162 hp; hp.x = ha; hp.y = hb;
    hi = *reinterpret_cast<uint32_t*>(&hp);
    lo = bf2(a - __bfloat162float(ha), b - __bfloat162float(hb));
}

__global__ void __launch_bounds__(TB, 1) autoreg_fused_kernel(
    const float* __restrict__ x,
    const float* __restrict__ W,
    const float* __restrict__ bia,
    const float* __restrict__ patchw,
    const float* __restrict__ pw1,
    const float* __restrict__ pb1,
    const float* __restrict__ pw2,
    const float* __restrict__ pb2,
    const float* __restrict__ projw,
    const float* __restrict__ projb,
    const float* __restrict__ dw,
    const float* __restrict__ db,
    const float* __restrict__ uw,
    const float* __restrict__ ub,
    float* __restrict__ out)
{
    extern __shared__ float sm[];
    char* smb = (char*)sm;
    const int tid  = threadIdx.x;
    const int wid  = tid >> 5;
    const int lid  = tid & 31;
    const int bidx = blockIdx.x;
    const uint32_t smem_base = smem_u32(sm);

    // ---- Load x row, bias vectors, raw patch weights ----
    for (int i = tid; i < DIMn; i += TB) {
        float xv = x[bidx * DIMn + i];
        sm[S_X + i]   = xv;
        sm[S_INV + i] = 1.0f / (fabsf(xv) + 1e-6f);
    }
    for (int i = tid; i < MIDn; i += TB) sm[S_DB + i] = db[i];
    for (int i = tid; i < HIDn; i += TB) sm[S_UB + i] = ub[i];
    if (tid < 64) sm[S_SW + tid] = patchw[tid];
    __syncthreads();

    // ---- Patch-weight softmax (thread 0; overlapped with stage A of other warps) ----
    if (tid == 0) {
        float m = -1e30f;
        for (int i = 0; i < 64; i++) m = fmaxf(m, sm[S_SW + i]);
        float s = 0.0f;
        for (int i = 0; i < 64; i++) { float e = expf(sm[S_SW + i] - m); sm[S_SW + i] = e; s += e; }
        float is = 1.0f / s;
        for (int i = 0; i < 64; i++) sm[S_SW + i] *= is;
    }

    // ---- Stage A: H[i,c] = gelu(x_i*W[i,c] + inv_i*b[i,c]) ----
    for (int t = tid; t < DIMn * HIDn; t += TB) {
        int i = t >> 6;
        float v = sm[S_X + i] * W[t] + sm[S_INV + i] * bia[t];
        sm[S_H + t] = gelu_exact(v);
    }
    __syncthreads();

    // ---- Stage B: Hw[h,k,c] = sum_l w[k,l] * H[h*8+l, c] ----
    for (int p = tid; p < Gn * HIDn; p += TB) {
        int h = p >> 6, c = p & 63;
        float hv[8];
        #pragma unroll
        for (int l = 0; l < 8; l++) hv[l] = sm[S_H + (h * 8 + l) * 64 + c];
        #pragma unroll
        for (int k = 0; k < 8; k++) {
            float acc = 0.0f;
            #pragma unroll
            for (int l = 0; l < 8; l++) acc = fmaf(sm[S_SW + k * 8 + l], hv[l], acc);
            sm[S_HW + h * HW_STRIDE + k * 64 + c] = acc;
        }
    }
    __syncthreads();

    // ---- Stage C: Pg[g,h] = sum_{kc<512} H[g,kc] * Hw[h,kc] ----
    {
        const int tg = tid >> 4;
        const int th = tid & 15;
        const int g0 = tg * 3, h0 = th * 3;
        float acc[3][3];
        #pragma unroll
        for (int a = 0; a < 3; a++)
            #pragma unroll
            for (int b2 = 0; b2 < 3; b2++) acc[a][b2] = 0.0f;

        const float2* H2  = (const float2*)&sm[S_H];
        const float2* HW2 = (const float2*)&sm[S_HW];
        #pragma unroll 4
        for (int kc2 = 0; kc2 < 256; kc2++) {
            float2 a0 = H2[(g0 + 0) * 256 + kc2];
            float2 a1 = H2[(g0 + 1) * 256 + kc2];
            float2 a2 = H2[(g0 + 2) * 256 + kc2];
            float2 b0 = HW2[(h0 + 0) * 257 + kc2];
            float2 b1 = HW2[(h0 + 1) * 257 + kc2];
            float2 b2 = HW2[(h0 + 2) * 257 + kc2];
            acc[0][0] = fmaf(a0.x, b0.x, fmaf(a0.y, b0.y, acc[0][0]));
            acc[0][1] = fmaf(a0.x, b1.x, fmaf(a0.y, b1.y, acc[0][1]));
            acc[0][2] = fmaf(a0.x, b2.x, fmaf(a0.y, b2.y, acc[0][2]));
            acc[1][0] = fmaf(a1.x, b0.x, fmaf(a1.y, b0.y, acc[1][0]));
            acc[1][1] = fmaf(a1.x, b1.x, fmaf(a1.y, b1.y, acc[1][1]));
            acc[1][2] = fmaf(a1.x, b2.x, fmaf(a1.y, b2.y, acc[1][2]));
            acc[2][0] = fmaf(a2.x, b0.x, fmaf(a2.y, b0.y, acc[2][0]));
            acc[2][1] = fmaf(a2.x, b1.x, fmaf(a2.y, b1.y, acc[2][1]));
            acc[2][2] = fmaf(a2.x, b2.x, fmaf(a2.y, b2.y, acc[2][2]));
        }
        #pragma unroll
        for (int a = 0; a < 3; a++)
            #pragma unroll
            for (int b2 = 0; b2 < 3; b2++)
                sm[S_PG + (g0 + a) * 48 + (h0 + b2)] = acc[a][b2];
    }
    __syncthreads();

    // ---- Stage D: elementwise affines + leaky ----
    for (int t = tid; t < Gn * Gn; t += TB) {
        float v = sm[S_PG + t];
        v = leaky(fmaf(v, pw1[t], pb1[t]));
        v = leaky(fmaf(v, pw2[t], pb2[t]));
        sm[S_PG + t] = v;
    }
    __syncthreads();

    // ---- Row softmax + row_weights ----
    if (tid < Gn) {
        const float* row = &sm[S_PG + tid * 48];
        float m = -1e30f;
        for (int h = 0; h < 48; h++) m = fmaxf(m, row[h]);
        float s = 0.0f;
        for (int h = 0; h < 48; h++) s += expf(row[h] - m);
        float inv_s = 1.0f / s;
        float rw = 0.0f;
        for (int h = 0; h < 48; h++) {
            float p = expf(row[h] - m) * inv_s;
            rw += 1.0f / (1.0f + p * p);
        }
        sm[S_RW + tid] = rw;
    }
    __syncthreads();

    // ---- scales[i] = row_weights . proj_w[i,:] + proj_b[i] ----
    for (int i = tid; i < DIMn; i += TB) {
        float acc = projb[i];
        const float* pr = &projw[i * Gn];
        #pragma unroll
        for (int g = 0; g < Gn; g++) acc = fmaf(sm[S_RW + g], pr[g], acc);
        sm[S_SC + i] = acc;
    }
    __syncthreads();

    // ---- A-split: Hs = H * scale -> bf16 hi/lo into padded union-region buffer ----
    // (Hw/Pg are dead by now; rows [128B hi][128B lo][16B pad], stride 272B)
    for (int t = tid; t < 12288; t += TB) {
        int r = t >> 5, c2 = t & 31;
        float sc = sm[S_SC + r];
        float v0 = sm[S_H + r * 64 + 2 * c2]     * sc;
        float v1 = sm[S_H + r * 64 + 2 * c2 + 1] * sc;
        uint32_t h, l; split2(v0, v1, h, l);
        *(uint32_t*)(smb + EB_AS + r * AS_STRIDE + c2 * 4)       = h;
        *(uint32_t*)(smb + EB_AS + r * AS_STRIDE + 128 + c2 * 4) = l;
    }

    // ---- Gather loop-invariant B fragments (weights) from GMEM into registers ----
    // mma m16n8k16 B frag: reg i holds {B[k0+8i+2*(t%4)][n0+t/4], B[k0+8i+2*(t%4)+1][...]}
    const int mt = wid >> 2;        // 0..1: m16 tile within 32-row chunk
    const int nq = wid & 3;         // 0..3: n-quarter
    const int bq = lid >> 2;        // t/4
    const int bk = 2 * (lid & 3);

    uint32_t bG1h[4][4][2], bG1l[4][4][2];      // GEMM1: B = dw^T, [j(n8)][s(k16)][i]
    #pragma unroll
    for (int j = 0; j < 4; j++)
        #pragma unroll
        for (int s = 0; s < 4; s++)
            #pragma unroll
            for (int i = 0; i < 2; i++) {
                const float* p = dw + (32 * nq + 8 * j + bq) * 64 + 16 * s + 8 * i + bk;
                split2(p[0], p[1], bG1h[j][s][i], bG1l[j][s][i]);
            }
    uint32_t bG2h[2][8][2], bG2l[2][8][2];      // GEMM2: B = uw^T
    #pragma unroll
    for (int j = 0; j < 2; j++)
        #pragma unroll
        for (int s = 0; s < 8; s++)
            #pragma unroll
            for (int i = 0; i < 2; i++) {
                const float* p = uw + (16 * nq + 8 * j + bq) * 128 + 16 * s + 8 * i + bk;
                split2(p[0], p[1], bG2h[j][s][i], bG2l[j][s][i]);
            }
    __syncthreads();   // A-split visible to all

    // ---- Stage E: 12 chunks of 32 rows; warp (mt,nq) ----
    const int arow  = (lid & 15);
    const int acolb = ((lid >> 4) << 3) * 2;    // byte offset of k-col within row
    #pragma unroll 2
    for (int ch = 0; ch < 12; ch++) {
        const int R = ch * 32 + mt * 16;
        const uint32_t zbB = EB_Z + (ch & 1) * Z_BUFSZ;       // byte offset
        const uint32_t zbS = smem_base + zbB;

        // GEMM1: D1[16 x 32] = Hs[16x64] @ dw^T[64 x (32nq..)], 3-term compensated
        float d[4][4];
        #pragma unroll
        for (int j = 0; j < 4; j++)
            #pragma unroll
            for (int q = 0; q < 4; q++) d[j][q] = 0.0f;

        #pragma unroll
        for (int s = 0; s < 4; s++) {
            uint32_t ah[4], al[4];
            uint32_t aaddr = smem_base + EB_AS + (R + arow) * AS_STRIDE + 32 * s + acolb;
            ldsm_x4(ah, aaddr);
            ldsm_x4(al, aaddr + 128);
            #pragma unroll
            for (int j = 0; j < 4; j++) {
                mma_bf16(d[j], ah, bG1h[j][s]);
                mma_bf16(d[j], ah, bG1l[j][s]);
                mma_bf16(d[j], al, bG1h[j][s]);
            }
        }

        // bias + leaky + split -> z buffer (rows [256B hi][256B lo][16B pad])
        {
            const int zr = mt * 16 + bq;
            #pragma unroll
            for (int j = 0; j < 4; j++) {
                int n0 = 32 * nq + 8 * j + bk;
                float v0 = leaky(d[j][0] + sm[S_DB + n0]);
                float v1 = leaky(d[j][1] + sm[S_DB + n0 + 1]);
                uint32_t h, l; split2(v0, v1, h, l);
                *(uint32_t*)(smb + zbB + zr * Z_STRIDE + n0 * 2)       = h;
                *(uint32_t*)(smb + zbB + zr * Z_STRIDE + 256 + n0 * 2) = l;
                v0 = leaky(d[j][2] + sm[S_DB + n0]);
                v1 = leaky(d[j][3] + sm[S_DB + n0 + 1]);
                split2(v0, v1, h, l);
                *(uint32_t*)(smb + zbB + (zr + 8) * Z_STRIDE + n0 * 2)       = h;
                *(uint32_t*)(smb + zbB + (zr + 8) * Z_STRIDE + 256 + n0 * 2) = l;
            }
        }
        __syncthreads();

        // GEMM2: D2[16 x 16] = z[16x128] @ uw^T[128 x (16nq..)]
        float e2[2][4];
        #pragma unroll
        for (int j = 0; j < 2; j++)
            #pragma unroll
            for (int q = 0; q < 4; q++) e2[j][q] = 0.0f;

        #pragma unroll
        for (int s = 0; s < 8; s++) {
            uint32_t ah[4], al[4];
            uint32_t za = zbS + (mt * 16 + arow) * Z_STRIDE + 32 * s + acolb;
            ldsm_x4(ah, za);
            ldsm_x4(al, za + 256);
            #pragma unroll
            for (int j = 0; j < 2; j++) {
                mma_bf16(e2[j], ah, bG2h[j][s]);
                mma_bf16(e2[j], ah, bG2l[j][s]);
                mma_bf16(e2[j], al, bG2h[j][s]);
            }
        }

        // bias + leaky -> GMEM
        #pragma unroll
        for (int j = 0; j < 2; j++) {
            int n0 = 16 * nq + 8 * j + bk;
            int r  = R + bq;
            float2 o;
            o.x = leaky(e2[j][0] + sm[S_UB + n0]);
            o.y = leaky(e2[j][1] + sm[S_UB + n0 + 1]);
            *(float2*)(out + ((size_t)(bidx * DIMn + r)) * 64 + n0) = o;
            o.x = leaky(e2[j][2] + sm[S_UB + n0]);
            o.y = leaky(e2[j][3] + sm[S_UB + n0 + 1]);
            *(float2*)(out + ((size_t)(bidx * DIMn + r + 8)) * 64 + n0) = o;
        }
        // no second sync: z is double-buffered
    }
}

extern "C" void kernel_launch(void* const* d_in, const int* in_sizes, int n_in,
                              void* d_out, int out_size) {
    (void)in_sizes; (void)n_in; (void)out_size;
    const float* x      = (const float*)d_in[0];
    const float* W      = (const float*)d_in[1];
    const float* bia    = (const float*)d_in[2];
    const float* patchw = (const float*)d_in[3];
    const float* pw1    = (const float*)d_in[4];
    const float* pb1    = (const float*)d_in[5];
    const float* pw2    = (const float*)d_in[6];
    const float* pb2    = (const float*)d_in[7];
    const float* projw  = (const float*)d_in[8];
    const float* projb  = (const float*)d_in[9];
    const float* dw     = (const float*)d_in[10];
    const float* db     = (const float*)d_in[11];
    const float* uw     = (const float*)d_in[12];
    const float* ub     = (const float*)d_in[13];
    float* out = (float*)d_out;

    cudaFuncSetAttribute(autoreg_fused_kernel,
                         cudaFuncAttributeMaxDynamicSharedMemorySize,
                         SMEM_FLOATS * sizeof(float));
    autoreg_fused_kernel<<<Bn, TB, SMEM_FLOATS * sizeof(float)>>>(
        x, W, bia, patchw, pw1, pb1, pw2, pb2, projw, projb, dw, db, uw, ub, out);
}

// round 6
// speedup vs baseline: 1.7445x; 1.1727x over previous
#include <cuda_runtime.h>
#include <cuda_bf16.h>
#include <math.h>
#include <stdint.h>

#define TB 256

#define Bn   1024
#define DIMn 384
#define HIDn 64
#define Gn   48
#define MIDn 128

// ---------------- Shared-memory byte map ----------------
// H split:  384 rows x 272B ([128B hi][128B lo][16B pad]), XOR-swizzled cols.   0..104447
// Hw split: 48 rows x 2048B ([1024B hi][1024B lo]), XOR-swizzled cols.     104448..202751
// Pg: 48x48 fp32                                                           202752..211967
// z double buffers overlay Hw region in stage E.
#define HS_STRIDE 272
#define HWB   104448
#define ZB    104448
#define Z_STRIDE 528
#define Z_BUFSZ 16896

#define S_PG  50688     // float index (= byte 202752)
#define S_X   52992
#define S_INV 53376
#define S_SW  53760
#define S_SC  53824
#define S_RW  54208
#define S_DB  54256
#define S_UB  54384
#define SMEM_FLOATS 54448   // 217792 bytes

// ---------------- mma.sync / ldmatrix helpers ----------------
__device__ __forceinline__ uint32_t smem_u32(const void* p) {
    uint32_t a;
    asm("{ .reg .u64 t; cvta.to.shared.u64 t, %1; cvt.u32.u64 %0, t; }" : "=r"(a) : "l"(p));
    return a;
}
__device__ __forceinline__ void mma_bf16(float* d, const uint32_t* a, const uint32_t* b) {
    asm volatile("mma.sync.aligned.m16n8k16.row.col.f32.bf16.bf16.f32 "
        "{%0,%1,%2,%3}, {%4,%5,%6,%7}, {%8,%9}, {%0,%1,%2,%3};"
        : "+f"(d[0]), "+f"(d[1]), "+f"(d[2]), "+f"(d[3])
        : "r"(a[0]), "r"(a[1]), "r"(a[2]), "r"(a[3]), "r"(b[0]), "r"(b[1]));
}
__device__ __forceinline__ void ldsm_x4(uint32_t* r, uint32_t addr) {
    asm volatile("ldmatrix.sync.aligned.m8n8.x4.shared.b16 {%0,%1,%2,%3}, [%4];"
        : "=r"(r[0]), "=r"(r[1]), "=r"(r[2]), "=r"(r[3]) : "r"(addr));
}

__device__ __forceinline__ float leaky(float v) { return (v >= 0.0f) ? v : 0.01f * v; }
__device__ __forceinline__ float gelu_exact(float v) {
    return 0.5f * v * (1.0f + erff(v * 0.70710678118654752f));
}
__device__ __forceinline__ uint32_t bf2(float a, float b) {
    __nv_bfloat162 t; t.x = __float2bfloat16(a); t.y = __float2bfloat16(b);
    return *reinterpret_cast<uint32_t*>(&t);
}
__device__ __forceinline__ void split2(float a, float b, uint32_t &hi, uint32_t &lo) {
    __nv_bfloat16 ha = __float2bfloat16(a);
    __nv_bfloat16 hb = __float2bfloat16(b);
    __nv_bfloat162 hp; hp.x = ha; hp.y = hb;
    hi = *reinterpret_cast<uint32_t*>(&hp);
    lo = bf2(a - __bfloat162float(ha), b - __bfloat162float(hb));
}
// byte address of hi word w (0..31) in swizzled H-split row i; lo = +128
__device__ __forceinline__ uint32_t hs_addr(int i, int w) {
    int s = (i >> 3) & 7;
    return (uint32_t)(i * HS_STRIDE + ((((w >> 2) ^ s) << 4) | ((w & 3) << 2)));
}

__global__ void __launch_bounds__(TB, 1) autoreg_fused_kernel(
    const float* __restrict__ x,
    const float* __restrict__ W,
    const float* __restrict__ bia,
    const float* __restrict__ patchw,
    const float* __restrict__ pw1,
    const float* __restrict__ pb1,
    const float* __restrict__ pw2,
    const float* __restrict__ pb2,
    const float* __restrict__ projw,
    const float* __restrict__ projb,
    const float* __restrict__ dw,
    const float* __restrict__ db,
    const float* __restrict__ uw,
    const float* __restrict__ ub,
    float* __restrict__ out)
{
    extern __shared__ float sm[];
    char* smb = (char*)sm;
    const int tid  = threadIdx.x;
    const int wid  = tid >> 5;
    const int lid  = tid & 31;
    const int bidx = blockIdx.x;
    const uint32_t smem_base = smem_u32(sm);

    // ---- Load x row, bias vectors, raw patch weights ----
    for (int i = tid; i < DIMn; i += TB) {
        float xv = x[bidx * DIMn + i];
        sm[S_X + i]   = xv;
        sm[S_INV + i] = 1.0f / (fabsf(xv) + 1e-6f);
    }
    for (int i = tid; i < MIDn; i += TB) sm[S_DB + i] = db[i];
    for (int i = tid; i < HIDn; i += TB) sm[S_UB + i] = ub[i];
    if (tid < 64) sm[S_SW + tid] = patchw[tid];
    __syncthreads();

    // ---- Patch-weight softmax (thread 0; overlaps stage A of other threads) ----
    if (tid == 0) {
        float m = -1e30f;
        for (int i = 0; i < 64; i++) m = fmaxf(m, sm[S_SW + i]);
        float s = 0.0f;
        for (int i = 0; i < 64; i++) { float e = expf(sm[S_SW + i] - m); sm[S_SW + i] = e; s += e; }
        float is = 1.0f / s;
        for (int i = 0; i < 64; i++) sm[S_SW + i] *= is;
    }

    // ---- Stage A: H = gelu(x*W + inv*b), written directly as bf16 hi/lo split ----
    for (int t = tid; t < 12288; t += TB) {
        int i = t >> 5, w = t & 31;
        float2 Wv = *(const float2*)(W + i * 64 + 2 * w);
        float2 Bv = *(const float2*)(bia + i * 64 + 2 * w);
        float xv = sm[S_X + i], iv = sm[S_INV + i];
        float v0 = gelu_exact(xv * Wv.x + iv * Bv.x);
        float v1 = gelu_exact(xv * Wv.y + iv * Bv.y);
        uint32_t h, l; split2(v0, v1, h, l);
        uint32_t a = hs_addr(i, w);
        *(uint32_t*)(smb + a)       = h;
        *(uint32_t*)(smb + a + 128) = l;
    }
    __syncthreads();

    // ---- Stage B: Hw[h][k*64+c] = sum_l w[k,l]*H[h8+l][c], emitted as bf16 hi/lo ----
    for (int t = tid; t < 1536; t += TB) {          // 48 h x 32 word-pairs
        int h = t >> 5, w = t & 31;
        float v0[8], v1[8];
        #pragma unroll
        for (int l = 0; l < 8; l++) {
            uint32_t a = hs_addr(h * 8 + l, w);
            uint32_t hw_ = *(uint32_t*)(smb + a);
            uint32_t lw_ = *(uint32_t*)(smb + a + 128);
            __nv_bfloat162 hb = *(__nv_bfloat162*)&hw_;
            __nv_bfloat162 lb = *(__nv_bfloat162*)&lw_;
            v0[l] = __bfloat162float(hb.x) + __bfloat162float(lb.x);
            v1[l] = __bfloat162float(hb.y) + __bfloat162float(lb.y);
        }
        int sh = h & 7;
        #pragma unroll
        for (int k = 0; k < 8; k++) {
            float a0 = 0.0f, a1 = 0.0f;
            #pragma unroll
            for (int l = 0; l < 8; l++) {
                float wv = sm[S_SW + k * 8 + l];
                a0 = fmaf(wv, v0[l], a0);
                a1 = fmaf(wv, v1[l], a1);
            }
            uint32_t hw2, lw2; split2(a0, a1, hw2, lw2);
            int W2 = k * 32 + w;
            uint32_t off = HWB + h * 2048 + ((((W2 >> 2) ^ sh) << 4) | ((W2 & 3) << 2));
            *(uint32_t*)(smb + off)        = hw2;
            *(uint32_t*)(smb + off + 1024) = lw2;
        }
    }
    __syncthreads();

    // ---- Stage C (tensor): Pg[48x48] = H(48x512) @ Hw^T, 3-term bf16 compensated ----
    if (wid < 6) {
        const int mtc = wid >> 1;       // 0..2 m16 tile
        const int nh  = wid & 1;        // 0..1 -> 3 n8 strips at 24*nh
        float acc[3][4];
        #pragma unroll
        for (int j = 0; j < 3; j++)
            #pragma unroll
            for (int q = 0; q < 4; q++) acc[j][q] = 0.0f;

        const int arow = lid & 15;
        const int ahalf = lid >> 4;                 // 0/1 -> k 0-7 / 8-15
        #pragma unroll 4
        for (int s = 0; s < 32; s++) {
            // A frags (hi/lo): rows i = (16*mtc + arow)*8 + (s>>2), 16B col (s&3)*2 + ahalf
            int i = (16 * mtc + arow) * 8 + (s >> 2);
            int colA = ((s & 3) * 2 + ahalf) ^ ((i >> 3) & 7);
            uint32_t aaddr = smem_base + i * HS_STRIDE + (colA << 4);
            uint32_t ah[4], al[4];
            ldsm_x4(ah, aaddr);
            ldsm_x4(al, aaddr + 128);
            #pragma unroll
            for (int j = 0; j < 3; j++) {
                // B frag x4: lanes 0-7 hi k0, 8-15 hi k8, 16-23 lo k0, 24-31 lo k8
                int hrow = 24 * nh + 8 * j + (lid & 7);
                int colB = (2 * s + ((lid >> 3) & 1)) ^ (hrow & 7);
                uint32_t baddr = smem_base + HWB + hrow * 2048 +
                                 ((lid >= 16) ? 1024 : 0) + (colB << 4);
                uint32_t bb[4];
                ldsm_x4(bb, baddr);
                mma_bf16(acc[j], ah, bb);       // Ahi*Bhi
                mma_bf16(acc[j], ah, bb + 2);   // Ahi*Blo
                mma_bf16(acc[j], al, bb);       // Alo*Bhi
            }
        }
        // write Pg
        #pragma unroll
        for (int j = 0; j < 3; j++) {
            int r = 16 * mtc + (lid >> 2);
            int c = 24 * nh + 8 * j + 2 * (lid & 3);
            *(float2*)&sm[S_PG + r * 48 + c]       = make_float2(acc[j][0], acc[j][1]);
            *(float2*)&sm[S_PG + (r + 8) * 48 + c] = make_float2(acc[j][2], acc[j][3]);
        }
    }
    __syncthreads();

    // ---- Stage D: elementwise affines + leaky ----
    for (int t = tid; t < Gn * Gn; t += TB) {
        float v = sm[S_PG + t];
        v = leaky(fmaf(v, pw1[t], pb1[t]));
        v = leaky(fmaf(v, pw2[t], pb2[t]));
        sm[S_PG + t] = v;
    }
    __syncthreads();

    // ---- Row softmax + row_weights (4 lanes per row) ----
    if (tid < 192) {
        int r = tid >> 2, q = tid & 3;
        const float* row = &sm[S_PG + r * 48 + q * 12];
        float m = -1e30f;
        #pragma unroll
        for (int h2 = 0; h2 < 12; h2++) m = fmaxf(m, row[h2]);
        m = fmaxf(m, __shfl_xor_sync(0xFFFFFFFF, m, 1));
        m = fmaxf(m, __shfl_xor_sync(0xFFFFFFFF, m, 2));
        float s = 0.0f;
        #pragma unroll
        for (int h2 = 0; h2 < 12; h2++) s += expf(row[h2] - m);
        s += __shfl_xor_sync(0xFFFFFFFF, s, 1);
        s += __shfl_xor_sync(0xFFFFFFFF, s, 2);
        float inv_s = 1.0f / s;
        float rw = 0.0f;
        #pragma unroll
        for (int h2 = 0; h2 < 12; h2++) {
            float p = expf(row[h2] - m) * inv_s;
            rw += 1.0f / (1.0f + p * p);
        }
        rw += __shfl_xor_sync(0xFFFFFFFF, rw, 1);
        rw += __shfl_xor_sync(0xFFFFFFFF, rw, 2);
        if (q == 0) sm[S_RW + r] = rw;
    }
    __syncthreads();

    // ---- scales[i] = row_weights . proj_w[i,:] + proj_b[i] ----
    for (int i = tid; i < DIMn; i += TB) {
        float acc = projb[i];
        const float* pr = &projw[i * Gn];
        #pragma unroll
        for (int g = 0; g < Gn; g++) acc = fmaf(sm[S_RW + g], pr[g], acc);
        sm[S_SC + i] = acc;
    }

    // ---- Gather loop-invariant weight B fragments from GMEM into registers ----
    const int mt = wid >> 2;        // 0..1
    const int nq = wid & 3;         // 0..3
    const int bq = lid >> 2;
    const int bk = 2 * (lid & 3);

    uint32_t bG1h[4][4][2], bG1l[4][4][2];
    #pragma unroll
    for (int j = 0; j < 4; j++)
        #pragma unroll
        for (int s = 0; s < 4; s++)
            #pragma unroll
            for (int i = 0; i < 2; i++) {
                const float* p = dw + (32 * nq + 8 * j + bq) * 64 + 16 * s + 8 * i + bk;
                split2(p[0], p[1], bG1h[j][s][i], bG1l[j][s][i]);
            }
    uint32_t bG2h[2][8][2], bG2l[2][8][2];
    #pragma unroll
    for (int j = 0; j < 2; j++)
        #pragma unroll
        for (int s = 0; s < 8; s++)
            #pragma unroll
            for (int i = 0; i < 2; i++) {
                const float* p = uw + (16 * nq + 8 * j + bq) * 128 + 16 * s + 8 * i + bk;
                split2(p[0], p[1], bG2h[j][s][i], bG2l[j][s][i]);
            }
    __syncthreads();   // scales visible; Hw region free for z buffers

    // ---- Stage E: 12 chunks of 32 rows; warp (mt,nq); scale applied to D1 rows ----
    const int arow  = lid & 15;
    const int ahalf = lid >> 4;
    #pragma unroll 2
    for (int ch = 0; ch < 12; ch++) {
        const int R = ch * 32 + mt * 16;
        const uint32_t zbB = ZB + (ch & 1) * Z_BUFSZ;
        const uint32_t zbS = smem_base + zbB;

        // GEMM1: D1[16 x 32] = H[16x64] @ dw^T strip
        float d[4][4];
        #pragma unroll
        for (int j = 0; j < 4; j++)
            #pragma unroll
            for (int q = 0; q < 4; q++) d[j][q] = 0.0f;

        #pragma unroll
        for (int s = 0; s < 4; s++) {
            int i = R + arow;
            int colA = (2 * s + ahalf) ^ ((i >> 3) & 7);
            uint32_t aaddr = smem_base + i * HS_STRIDE + (colA << 4);
            uint32_t ah[4], al[4];
            ldsm_x4(ah, aaddr);
            ldsm_x4(al, aaddr + 128);
            #pragma unroll
            for (int j = 0; j < 4; j++) {
                mma_bf16(d[j], ah, bG1h[j][s]);
                mma_bf16(d[j], ah, bG1l[j][s]);
                mma_bf16(d[j], al, bG1h[j][s]);
            }
        }

        // scale rows + bias + leaky + split -> z buffer
        {
            const int zr = mt * 16 + bq;
            const float s0 = sm[S_SC + ch * 32 + zr];
            const float s1 = sm[S_SC + ch * 32 + zr + 8];
            #pragma unroll
            for (int j = 0; j < 4; j++) {
                int n0 = 32 * nq + 8 * j + bk;
                float v0 = leaky(fmaf(d[j][0], s0, sm[S_DB + n0]));
                float v1 = leaky(fmaf(d[j][1], s0, sm[S_DB + n0 + 1]));
                uint32_t h, l; split2(v0, v1, h, l);
                *(uint32_t*)(smb + zbB + zr * Z_STRIDE + n0 * 2)       = h;
                *(uint32_t*)(smb + zbB + zr * Z_STRIDE + 256 + n0 * 2) = l;
                v0 = leaky(fmaf(d[j][2], s1, sm[S_DB + n0]));
                v1 = leaky(fmaf(d[j][3], s1, sm[S_DB + n0 + 1]));
                split2(v0, v1, h, l);
                *(uint32_t*)(smb + zbB + (zr + 8) * Z_STRIDE + n0 * 2)       = h;
                *(uint32_t*)(smb + zbB + (zr + 8) * Z_STRIDE + 256 + n0 * 2) = l;
            }
        }
        __syncthreads();

        // GEMM2: D2[16 x 16] = z[16x128] @ uw^T strip
        float e2[2][4];
        #pragma unroll
        for (int j = 0; j < 2; j++)
            #pragma unroll
            for (int q = 0; q < 4; q++) e2[j][q] = 0.0f;

        #pragma unroll
        for (int s = 0; s < 8; s++) {
            uint32_t ah[4], al[4];
            uint32_t za = zbS + (mt * 16 + arow) * Z_STRIDE + 32 * s + ahalf * 16;
            ldsm_x4(ah, za);
            ldsm_x4(al, za + 256);
            #pragma unroll
            for (int j = 0; j < 2; j++) {
                mma_bf16(e2[j], ah, bG2h[j][s]);
                mma_bf16(e2[j], ah, bG2l[j][s]);
                mma_bf16(e2[j], al, bG2h[j][s]);
            }
        }

        // bias + leaky -> GMEM
        #pragma unroll
        for (int j = 0; j < 2; j++) {
            int n0 = 16 * nq + 8 * j + bk;
            int r  = R + bq;
            float2 o;
            o.x = leaky(e2[j][0] + sm[S_UB + n0]);
            o.y = leaky(e2[j][1] + sm[S_UB + n0 + 1]);
            *(float2*)(out + ((size_t)(bidx * DIMn + r)) * 64 + n0) = o;
            o.x = leaky(e2[j][2] + sm[S_UB + n0]);
            o.y = leaky(e2[j][3] + sm[S_UB + n0 + 1]);
            *(float2*)(out + ((size_t)(bidx * DIMn + r + 8)) * 64 + n0) = o;
        }
        // z double-buffered: next overwrite of this buffer happens after next sync
    }
}

extern "C" void kernel_launch(void* const* d_in, const int* in_sizes, int n_in,
                              void* d_out, int out_size) {
    (void)in_sizes; (void)n_in; (void)out_size;
    const float* x      = (const float*)d_in[0];
    const float* W      = (const float*)d_in[1];
    const float* bia    = (const float*)d_in[2];
    const float* patchw = (const float*)d_in[3];
    const float* pw1    = (const float*)d_in[4];
    const float* pb1    = (const float*)d_in[5];
    const float* pw2    = (const float*)d_in[6];
    const float* pb2    = (const float*)d_in[7];
    const float* projw  = (const float*)d_in[8];
    const float* projb  = (const float*)d_in[9];
    const float* dw     = (const float*)d_in[10];
    const float* db     = (const float*)d_in[11];
    const float* uw     = (const float*)d_in[12];
    const float* ub     = (const float*)d_in[13];
    float* out = (float*)d_out;

    cudaFuncSetAttribute(autoreg_fused_kernel,
                         cudaFuncAttributeMaxDynamicSharedMemorySize,
                         SMEM_FLOATS * sizeof(float));
    autoreg_fused_kernel<<<Bn, TB, SMEM_FLOATS * sizeof(float)>>>(
        x, W, bia, patchw, pw1, pb1, pw2, pb2, projw, projb, dw, db, uw, ub, out);
}

// round 7
// speedup vs baseline: 1.7628x; 1.0105x over previous
#include <cuda_runtime.h>
#include <cuda_bf16.h>
#include <math.h>
#include <stdint.h>

#define TB 512

#define Bn   1024
#define DIMn 384
#define HIDn 64
#define Gn   48
#define MIDn 128

// ---------------- Shared-memory byte map ----------------
// H split:  384 rows x 272B ([128B hi][128B lo][16B pad]), XOR-swizzled cols.   0..104447
// Hw split: 48 rows x 2048B ([1024B hi][1024B lo]), XOR-swizzled cols.     104448..202751
// Pg: 48x48 fp32                                                           202752..211967
// z double buffers overlay Hw region in stage E.
#define HS_STRIDE 272
#define HWB   104448
#define ZB    104448
#define Z_STRIDE 528
#define Z_BUFSZ 16896

#define S_PG  50688     // float index (= byte 202752)
#define S_X   52992
#define S_INV 53376
#define S_SW  53760
#define S_SC  53824
#define S_RW  54208
#define S_DB  54256
#define S_UB  54384
#define SMEM_FLOATS 54448   // 217792 bytes

// ---------------- mma.sync / ldmatrix helpers ----------------
__device__ __forceinline__ uint32_t smem_u32(const void* p) {
    uint32_t a;
    asm("{ .reg .u64 t; cvta.to.shared.u64 t, %1; cvt.u32.u64 %0, t; }" : "=r"(a) : "l"(p));
    return a;
}
__device__ __forceinline__ void mma_bf16(float* d, const uint32_t* a, const uint32_t* b) {
    asm volatile("mma.sync.aligned.m16n8k16.row.col.f32.bf16.bf16.f32 "
        "{%0,%1,%2,%3}, {%4,%5,%6,%7}, {%8,%9}, {%0,%1,%2,%3};"
        : "+f"(d[0]), "+f"(d[1]), "+f"(d[2]), "+f"(d[3])
        : "r"(a[0]), "r"(a[1]), "r"(a[2]), "r"(a[3]), "r"(b[0]), "r"(b[1]));
}
__device__ __forceinline__ void ldsm_x4(uint32_t* r, uint32_t addr) {
    asm volatile("ldmatrix.sync.aligned.m8n8.x4.shared.b16 {%0,%1,%2,%3}, [%4];"
        : "=r"(r[0]), "=r"(r[1]), "=r"(r[2]), "=r"(r[3]) : "r"(addr));
}

__device__ __forceinline__ float leaky(float v) { return (v >= 0.0f) ? v : 0.01f * v; }
__device__ __forceinline__ float gelu_exact(float v) {
    return 0.5f * v * (1.0f + erff(v * 0.70710678118654752f));
}
__device__ __forceinline__ uint32_t bf2(float a, float b) {
    __nv_bfloat162 t; t.x = __float2bfloat16(a); t.y = __float2bfloat16(b);
    return *reinterpret_cast<uint32_t*>(&t);
}
__device__ __forceinline__ void split2(float a, float b, uint32_t &hi, uint32_t &lo) {
    __nv_bfloat16 ha = __float2bfloat16(a);
    __nv_bfloat16 hb = __float2bfloat16(b);
    __nv_bfloat162 hp; hp.x = ha; hp.y = hb;
    hi = *reinterpret_cast<uint32_t*>(&hp);
    lo = bf2(a - __bfloat162float(ha), b - __bfloat162float(hb));
}
__device__ __forceinline__ uint32_t hs_addr(int i, int w) {
    int s = (i >> 3) & 7;
    return (uint32_t)(i * HS_STRIDE + ((((w >> 2) ^ s) << 4) | ((w & 3) << 2)));
}

__global__ void __launch_bounds__(TB, 1) autoreg_fused_kernel(
    const float* __restrict__ x,
    const float* __restrict__ W,
    const float* __restrict__ bia,
    const float* __restrict__ patchw,
    const float* __restrict__ pw1,
    const float* __restrict__ pb1,
    const float* __restrict__ pw2,
    const float* __restrict__ pb2,
    const float* __restrict__ projw,
    const float* __restrict__ projb,
    const float* __restrict__ dw,
    const float* __restrict__ db,
    const float* __restrict__ uw,
    const float* __restrict__ ub,
    float* __restrict__ out)
{
    extern __shared__ float sm[];
    char* smb = (char*)sm;
    const int tid  = threadIdx.x;
    const int wid  = tid >> 5;
    const int lid  = tid & 31;
    const int bidx = blockIdx.x;
    const uint32_t smem_base = smem_u32(sm);

    // ---- Load x row, bias vectors, raw patch weights ----
    for (int i = tid; i < DIMn; i += TB) {
        float xv = x[bidx * DIMn + i];
        sm[S_X + i]   = xv;
        sm[S_INV + i] = 1.0f / (fabsf(xv) + 1e-6f);
    }
    if (tid < MIDn) sm[S_DB + tid] = db[tid];
    if (tid >= 128 && tid < 192) sm[S_UB + tid - 128] = ub[tid - 128];
    if (tid >= 192 && tid < 256) sm[S_SW + tid - 192] = patchw[tid - 192];
    __syncthreads();

    // ---- Patch-weight softmax (thread 0; overlaps stage A of other threads) ----
    if (tid == 0) {
        float m = -1e30f;
        for (int i = 0; i < 64; i++) m = fmaxf(m, sm[S_SW + i]);
        float s = 0.0f;
        for (int i = 0; i < 64; i++) { float e = expf(sm[S_SW + i] - m); sm[S_SW + i] = e; s += e; }
        float is = 1.0f / s;
        for (int i = 0; i < 64; i++) sm[S_SW + i] *= is;
    }

    // ---- Stage A: H = gelu(x*W + inv*b), written directly as bf16 hi/lo split ----
    for (int t = tid; t < 12288; t += TB) {
        int i = t >> 5, w = t & 31;
        float2 Wv = *(const float2*)(W + i * 64 + 2 * w);
        float2 Bv = *(const float2*)(bia + i * 64 + 2 * w);
        float xv = sm[S_X + i], iv = sm[S_INV + i];
        float v0 = gelu_exact(xv * Wv.x + iv * Bv.x);
        float v1 = gelu_exact(xv * Wv.y + iv * Bv.y);
        uint32_t h, l; split2(v0, v1, h, l);
        uint32_t a = hs_addr(i, w);
        *(uint32_t*)(smb + a)       = h;
        *(uint32_t*)(smb + a + 128) = l;
    }
    __syncthreads();

    // ---- Stage B: Hw[h][k*64+c] = sum_l w[k,l]*H[h8+l][c], emitted as bf16 hi/lo ----
    for (int t = tid; t < 1536; t += TB) {
        int h = t >> 5, w = t & 31;
        float v0[8], v1[8];
        #pragma unroll
        for (int l = 0; l < 8; l++) {
            uint32_t a = hs_addr(h * 8 + l, w);
            uint32_t hw_ = *(uint32_t*)(smb + a);
            uint32_t lw_ = *(uint32_t*)(smb + a + 128);
            __nv_bfloat162 hb = *(__nv_bfloat162*)&hw_;
            __nv_bfloat162 lb = *(__nv_bfloat162*)&lw_;
            v0[l] = __bfloat162float(hb.x) + __bfloat162float(lb.x);
            v1[l] = __bfloat162float(hb.y) + __bfloat162float(lb.y);
        }
        int sh = h & 7;
        #pragma unroll
        for (int k = 0; k < 8; k++) {
            float a0 = 0.0f, a1 = 0.0f;
            #pragma unroll
            for (int l = 0; l < 8; l++) {
                float wv = sm[S_SW + k * 8 + l];
                a0 = fmaf(wv, v0[l], a0);
                a1 = fmaf(wv, v1[l], a1);
            }
            uint32_t hw2, lw2; split2(a0, a1, hw2, lw2);
            int W2 = k * 32 + w;
            uint32_t off = HWB + h * 2048 + ((((W2 >> 2) ^ sh) << 4) | ((W2 & 3) << 2));
            *(uint32_t*)(smb + off)        = hw2;
            *(uint32_t*)(smb + off + 1024) = lw2;
        }
    }
    __syncthreads();

    // ---- Gather loop-invariant weight B fragments (overlaps stage C below) ----
    // warps 0-7: GEMM1 (dw), warps 8-15: GEMM2 (uw). 32 hi/lo pairs each.
    const int eg = wid >> 3;            // 0 = GEMM1 group, 1 = GEMM2 group
    const int mt = (wid >> 2) & 1;
    const int nq = wid & 3;
    const int bq = lid >> 2;
    const int bk = 2 * (lid & 3);

    uint32_t bWh[32], bWl[32];
    if (eg == 0) {
        #pragma unroll
        for (int j = 0; j < 4; j++)
            #pragma unroll
            for (int s = 0; s < 4; s++)
                #pragma unroll
                for (int i = 0; i < 2; i++) {
                    const float* p = dw + (32 * nq + 8 * j + bq) * 64 + 16 * s + 8 * i + bk;
                    split2(p[0], p[1], bWh[(j * 4 + s) * 2 + i], bWl[(j * 4 + s) * 2 + i]);
                }
    } else {
        #pragma unroll
        for (int j = 0; j < 2; j++)
            #pragma unroll
            for (int s = 0; s < 8; s++)
                #pragma unroll
                for (int i = 0; i < 2; i++) {
                    const float* p = uw + (16 * nq + 8 * j + bq) * 128 + 16 * s + 8 * i + bk;
                    split2(p[0], p[1], bWh[(j * 8 + s) * 2 + i], bWl[(j * 8 + s) * 2 + i]);
                }
    }

    // ---- Stage C (tensor, warps 0-5): Pg[48x48] = H(48x512) @ Hw^T ----
    if (wid < 6) {
        const int mtc = wid >> 1;
        const int nh  = wid & 1;
        float acc[3][4];
        #pragma unroll
        for (int j = 0; j < 3; j++)
            #pragma unroll
            for (int q = 0; q < 4; q++) acc[j][q] = 0.0f;

        const int arow = lid & 15;
        const int ahalf = lid >> 4;
        #pragma unroll 4
        for (int s = 0; s < 32; s++) {
            int i = (16 * mtc + arow) * 8 + (s >> 2);
            int colA = ((s & 3) * 2 + ahalf) ^ ((i >> 3) & 7);
            uint32_t aaddr = smem_base + i * HS_STRIDE + (colA << 4);
            uint32_t ah[4], al[4];
            ldsm_x4(ah, aaddr);
            ldsm_x4(al, aaddr + 128);
            #pragma unroll
            for (int j = 0; j < 3; j++) {
                int hrow = 24 * nh + 8 * j + (lid & 7);
                int colB = (2 * s + ((lid >> 3) & 1)) ^ (hrow & 7);
                uint32_t baddr = smem_base + HWB + hrow * 2048 +
                                 ((lid >= 16) ? 1024 : 0) + (colB << 4);
                uint32_t bb[4];
                ldsm_x4(bb, baddr);
                mma_bf16(acc[j], ah, bb);
                mma_bf16(acc[j], ah, bb + 2);
                mma_bf16(acc[j], al, bb);
            }
        }
        #pragma unroll
        for (int j = 0; j < 3; j++) {
            int r = 16 * mtc + (lid >> 2);
            int c = 24 * nh + 8 * j + 2 * (lid & 3);
            *(float2*)&sm[S_PG + r * 48 + c]       = make_float2(acc[j][0], acc[j][1]);
            *(float2*)&sm[S_PG + (r + 8) * 48 + c] = make_float2(acc[j][2], acc[j][3]);
        }
    }
    __syncthreads();

    // ---- Stage D: elementwise affines + leaky ----
    for (int t = tid; t < Gn * Gn; t += TB) {
        float v = sm[S_PG + t];
        v = leaky(fmaf(v, pw1[t], pb1[t]));
        v = leaky(fmaf(v, pw2[t], pb2[t]));
        sm[S_PG + t] = v;
    }
    __syncthreads();

    // ---- Row softmax + row_weights (4 lanes per row) ----
    if (tid < 192) {
        int r = tid >> 2, q = tid & 3;
        const float* row = &sm[S_PG + r * 48 + q * 12];
        float m = -1e30f;
        #pragma unroll
        for (int h2 = 0; h2 < 12; h2++) m = fmaxf(m, row[h2]);
        m = fmaxf(m, __shfl_xor_sync(0xFFFFFFFF, m, 1));
        m = fmaxf(m, __shfl_xor_sync(0xFFFFFFFF, m, 2));
        float s = 0.0f;
        #pragma unroll
        for (int h2 = 0; h2 < 12; h2++) s += expf(row[h2] - m);
        s += __shfl_xor_sync(0xFFFFFFFF, s, 1);
        s += __shfl_xor_sync(0xFFFFFFFF, s, 2);
        float inv_s = 1.0f / s;
        float rw = 0.0f;
        #pragma unroll
        for (int h2 = 0; h2 < 12; h2++) {
            float p = expf(row[h2] - m) * inv_s;
            rw += 1.0f / (1.0f + p * p);
        }
        rw += __shfl_xor_sync(0xFFFFFFFF, rw, 1);
        rw += __shfl_xor_sync(0xFFFFFFFF, rw, 2);
        if (q == 0) sm[S_RW + r] = rw;
    }
    __syncthreads();

    // ---- scales[i] = row_weights . proj_w[i,:] + proj_b[i] ----
    if (tid < DIMn) {
        float acc = projb[tid];
        const float* pr = &projw[tid * Gn];
        #pragma unroll
        for (int g = 0; g < Gn; g++) acc = fmaf(sm[S_RW + g], pr[g], acc);
        sm[S_SC + tid] = acc;
    }
    __syncthreads();   // scales visible; Hw region free for z buffers

    // ---- Stage E: warp-specialized pipeline over 12 chunks of 32 rows ----
    // warps 0-7 produce z (GEMM1+scale+bias+leaky+split); warps 8-15 consume (GEMM2+out).
    const int arow  = lid & 15;
    const int ahalf = lid >> 4;

    for (int it = 0; it <= 12; it++) {
        if (eg == 0 && it < 12) {
            const int ch = it;
            const int R = ch * 32 + mt * 16;
            const uint32_t zbB = ZB + (ch & 1) * Z_BUFSZ;

            float d[4][4];
            #pragma unroll
            for (int j = 0; j < 4; j++)
                #pragma unroll
                for (int q = 0; q < 4; q++) d[j][q] = 0.0f;

            #pragma unroll
            for (int s = 0; s < 4; s++) {
                int i = R + arow;
                int colA = (2 * s + ahalf) ^ ((i >> 3) & 7);
                uint32_t aaddr = smem_base + i * HS_STRIDE + (colA << 4);
                uint32_t ah[4], al[4];
                ldsm_x4(ah, aaddr);
                ldsm_x4(al, aaddr + 128);
                #pragma unroll
                for (int j = 0; j < 4; j++) {
                    mma_bf16(d[j], ah, &bWh[(j * 4 + s) * 2]);
                    mma_bf16(d[j], ah, &bWl[(j * 4 + s) * 2]);
                    mma_bf16(d[j], al, &bWh[(j * 4 + s) * 2]);
                }
            }

            const int zr = mt * 16 + bq;
            const float s0 = sm[S_SC + ch * 32 + zr];
            const float s1 = sm[S_SC + ch * 32 + zr + 8];
            #pragma unroll
            for (int j = 0; j < 4; j++) {
                int n0 = 32 * nq + 8 * j + bk;
                float v0 = leaky(fmaf(d[j][0], s0, sm[S_DB + n0]));
                float v1 = leaky(fmaf(d[j][1], s0, sm[S_DB + n0 + 1]));
                uint32_t h, l; split2(v0, v1, h, l);
                *(uint32_t*)(smb + zbB + zr * Z_STRIDE + n0 * 2)       = h;
                *(uint32_t*)(smb + zbB + zr * Z_STRIDE + 256 + n0 * 2) = l;
                v0 = leaky(fmaf(d[j][2], s1, sm[S_DB + n0]));
                v1 = leaky(fmaf(d[j][3], s1, sm[S_DB + n0 + 1]));
                split2(v0, v1, h, l);
                *(uint32_t*)(smb + zbB + (zr + 8) * Z_STRIDE + n0 * 2)       = h;
                *(uint32_t*)(smb + zbB + (zr + 8) * Z_STRIDE + 256 + n0 * 2) = l;
            }
        }
        if (eg == 1 && it >= 1) {
            const int ch = it - 1;
            const int R = ch * 32 + mt * 16;
            const uint32_t zbS = smem_base + ZB + (ch & 1) * Z_BUFSZ;

            float e2[2][4];
            #pragma unroll
            for (int j = 0; j < 2; j++)
                #pragma unroll
                for (int q = 0; q < 4; q++) e2[j][q] = 0.0f;

            #pragma unroll
            for (int s = 0; s < 8; s++) {
                uint32_t ah[4], al[4];
                uint32_t za = zbS + (mt * 16 + arow) * Z_STRIDE + 32 * s + ahalf * 16;
                ldsm_x4(ah, za);
                ldsm_x4(al, za + 256);
                #pragma unroll
                for (int j = 0; j < 2; j++) {
                    mma_bf16(e2[j], ah, &bWh[(j * 8 + s) * 2]);
                    mma_bf16(e2[j], ah, &bWl[(j * 8 + s) * 2]);
                    mma_bf16(e2[j], al, &bWh[(j * 8 + s) * 2]);
                }
            }

            #pragma unroll
            for (int j = 0; j < 2; j++) {
                int n0 = 16 * nq + 8 * j + bk;
                int r  = R + bq;
                float2 o;
                o.x = leaky(e2[j][0] + sm[S_UB + n0]);
                o.y = leaky(e2[j][1] + sm[S_UB + n0 + 1]);
                *(float2*)(out + ((size_t)(bidx * DIMn + r)) * 64 + n0) = o;
                o.x = leaky(e2[j][2] + sm[S_UB + n0]);
                o.y = leaky(e2[j][3] + sm[S_UB + n0 + 1]);
                *(float2*)(out + ((size_t)(bidx * DIMn + r + 8)) * 64 + n0) = o;
            }
        }
        __syncthreads();
    }
}

extern "C" void kernel_launch(void* const* d_in, const int* in_sizes, int n_in,
                              void* d_out, int out_size) {
    (void)in_sizes; (void)n_in; (void)out_size;
    const float* x      = (const float*)d_in[0];
    const float* W      = (const float*)d_in[1];
    const float* bia    = (const float*)d_in[2];
    const float* patchw = (const float*)d_in[3];
    const float* pw1    = (const float*)d_in[4];
    const float* pb1    = (const float*)d_in[5];
    const float* pw2    = (const float*)d_in[6];
    const float* pb2    = (const float*)d_in[7];
    const float* projw  = (const float*)d_in[8];
    const float* projb  = (const float*)d_in[9];
    const float* dw     = (const float*)d_in[10];
    const float* db     = (const float*)d_in[11];
    const float* uw     = (const float*)d_in[12];
    const float* ub     = (const float*)d_in[13];
    float* out = (float*)d_out;

    cudaFuncSetAttribute(autoreg_fused_kernel,
                         cudaFuncAttributeMaxDynamicSharedMemorySize,
                         SMEM_FLOATS * sizeof(float));
    autoreg_fused_kernel<<<Bn, TB, SMEM_FLOATS * sizeof(float)>>>(
        x, W, bia, patchw, pw1, pb1, pw2, pb2, projw, projb, dw, db, uw, ub, out);
}

// round 8
// speedup vs baseline: 1.8019x; 1.0222x over previous
#include <cuda_runtime.h>
#include <cuda_bf16.h>
#include <math.h>
#include <stdint.h>

#define TB 512

#define Bn   1024
#define DIMn 384
#define HIDn 64
#define Gn   48
#define MIDn 128

// ---------------- Shared-memory byte map ----------------
#define HS_STRIDE 272
#define HWB   104448
#define ZB    104448
#define Z_STRIDE 528
#define Z_BUFSZ 16896

#define S_PG  50688
#define S_X   52992
#define S_INV 53376
#define S_SW  53760
#define S_SC  53824
#define S_RW  54208
#define S_DB  54256
#define S_UB  54384
#define SMEM_FLOATS 54448   // 217792 bytes

// ---------------- mma.sync / ldmatrix helpers ----------------
__device__ __forceinline__ uint32_t smem_u32(const void* p) {
    uint32_t a;
    asm("{ .reg .u64 t; cvta.to.shared.u64 t, %1; cvt.u32.u64 %0, t; }" : "=r"(a) : "l"(p));
    return a;
}
__device__ __forceinline__ void mma_bf16(float* d, const uint32_t* a, const uint32_t* b) {
    asm volatile("mma.sync.aligned.m16n8k16.row.col.f32.bf16.bf16.f32 "
        "{%0,%1,%2,%3}, {%4,%5,%6,%7}, {%8,%9}, {%0,%1,%2,%3};"
        : "+f"(d[0]), "+f"(d[1]), "+f"(d[2]), "+f"(d[3])
        : "r"(a[0]), "r"(a[1]), "r"(a[2]), "r"(a[3]), "r"(b[0]), "r"(b[1]));
}
__device__ __forceinline__ void ldsm_x4(uint32_t* r, uint32_t addr) {
    asm volatile("ldmatrix.sync.aligned.m8n8.x4.shared.b16 {%0,%1,%2,%3}, [%4];"
        : "=r"(r[0]), "=r"(r[1]), "=r"(r[2]), "=r"(r[3]) : "r"(addr));
}

__device__ __forceinline__ float leaky(float v) { return (v >= 0.0f) ? v : 0.01f * v; }
__device__ __forceinline__ float gelu_exact(float v) {
    return 0.5f * v * (1.0f + erff(v * 0.70710678118654752f));
}
__device__ __forceinline__ uint32_t bf2(float a, float b) {
    __nv_bfloat162 t; t.x = __float2bfloat16(a); t.y = __float2bfloat16(b);
    return *reinterpret_cast<uint32_t*>(&t);
}
__device__ __forceinline__ void split2(float a, float b, uint32_t &hi, uint32_t &lo) {
    __nv_bfloat16 ha = __float2bfloat16(a);
    __nv_bfloat16 hb = __float2bfloat16(b);
    __nv_bfloat162 hp; hp.x = ha; hp.y = hb;
    hi = *reinterpret_cast<uint32_t*>(&hp);
    lo = bf2(a - __bfloat162float(ha), b - __bfloat162float(hb));
}
__device__ __forceinline__ uint32_t hs_addr(int i, int w) {
    int s = (i >> 3) & 7;
    return (uint32_t)(i * HS_STRIDE + ((((w >> 2) ^ s) << 4) | ((w & 3) << 2)));
}

__global__ void __launch_bounds__(TB, 1) autoreg_fused_kernel(
    const float* __restrict__ x,
    const float* __restrict__ W,
    const float* __restrict__ bia,
    const float* __restrict__ patchw,
    const float* __restrict__ pw1,
    const float* __restrict__ pb1,
    const float* __restrict__ pw2,
    const float* __restrict__ pb2,
    const float* __restrict__ projw,
    const float* __restrict__ projb,
    const float* __restrict__ dw,
    const float* __restrict__ db,
    const float* __restrict__ uw,
    const float* __restrict__ ub,
    float* __restrict__ out)
{
    extern __shared__ float sm[];
    char* smb = (char*)sm;
    const int tid  = threadIdx.x;
    const int wid  = tid >> 5;
    const int lid  = tid & 31;
    const int bidx = blockIdx.x;
    const uint32_t smem_base = smem_u32(sm);

    // ---- Load x row, bias vectors, raw patch weights ----
    for (int i = tid; i < DIMn; i += TB) {
        float xv = x[bidx * DIMn + i];
        sm[S_X + i]   = xv;
        sm[S_INV + i] = 1.0f / (fabsf(xv) + 1e-6f);
    }
    if (tid < MIDn) sm[S_DB + tid] = db[tid];
    if (tid >= 128 && tid < 192) sm[S_UB + tid - 128] = ub[tid - 128];
    if (tid >= 192 && tid < 256) sm[S_SW + tid - 192] = patchw[tid - 192];
    __syncthreads();

    // ---- Patch-weight softmax (thread 0; overlaps stage A) ----
    if (tid == 0) {
        float m = -1e30f;
        for (int i = 0; i < 64; i++) m = fmaxf(m, sm[S_SW + i]);
        float s = 0.0f;
        for (int i = 0; i < 64; i++) { float e = expf(sm[S_SW + i] - m); sm[S_SW + i] = e; s += e; }
        float is = 1.0f / s;
        for (int i = 0; i < 64; i++) sm[S_SW + i] *= is;
    }

    // ---- Stage A: H = gelu(x*W + inv*b), written as bf16 hi/lo split ----
    for (int t = tid; t < 12288; t += TB) {
        int i = t >> 5, w = t & 31;
        float2 Wv = *(const float2*)(W + i * 64 + 2 * w);
        float2 Bv = *(const float2*)(bia + i * 64 + 2 * w);
        float xv = sm[S_X + i], iv = sm[S_INV + i];
        float v0 = gelu_exact(xv * Wv.x + iv * Bv.x);
        float v1 = gelu_exact(xv * Wv.y + iv * Bv.y);
        uint32_t h, l; split2(v0, v1, h, l);
        uint32_t a = hs_addr(i, w);
        *(uint32_t*)(smb + a)       = h;
        *(uint32_t*)(smb + a + 128) = l;
    }
    __syncthreads();

    // ---- Stage B: Hw ----
    for (int t = tid; t < 1536; t += TB) {
        int h = t >> 5, w = t & 31;
        float v0[8], v1[8];
        #pragma unroll
        for (int l = 0; l < 8; l++) {
            uint32_t a = hs_addr(h * 8 + l, w);
            uint32_t hw_ = *(uint32_t*)(smb + a);
            uint32_t lw_ = *(uint32_t*)(smb + a + 128);
            __nv_bfloat162 hb = *(__nv_bfloat162*)&hw_;
            __nv_bfloat162 lb = *(__nv_bfloat162*)&lw_;
            v0[l] = __bfloat162float(hb.x) + __bfloat162float(lb.x);
            v1[l] = __bfloat162float(hb.y) + __bfloat162float(lb.y);
        }
        int sh = h & 7;
        #pragma unroll
        for (int k = 0; k < 8; k++) {
            float a0 = 0.0f, a1 = 0.0f;
            #pragma unroll
            for (int l = 0; l < 8; l++) {
                float wv = sm[S_SW + k * 8 + l];
                a0 = fmaf(wv, v0[l], a0);
                a1 = fmaf(wv, v1[l], a1);
            }
            uint32_t hw2, lw2; split2(a0, a1, hw2, lw2);
            int W2 = k * 32 + w;
            uint32_t off = HWB + h * 2048 + ((((W2 >> 2) ^ sh) << 4) | ((W2 & 3) << 2));
            *(uint32_t*)(smb + off)        = hw2;
            *(uint32_t*)(smb + off + 1024) = lw2;
        }
    }
    __syncthreads();

    // ---- Gather loop-invariant weight B fragments (overlaps stage C) ----
    // Producers (warps 0-7): n16 strip of dw. Consumers (warps 8-15): n8 strip of uw.
    const int eg = wid >> 3;
    const int sn = wid & 7;             // strip index within group
    const int bq = lid >> 2;
    const int bk = 2 * (lid & 3);

    uint32_t bWh[16], bWl[16];
    if (eg == 0) {
        #pragma unroll
        for (int j = 0; j < 2; j++)
            #pragma unroll
            for (int s = 0; s < 4; s++)
                #pragma unroll
                for (int i = 0; i < 2; i++) {
                    const float* p = dw + (16 * sn + 8 * j + bq) * 64 + 16 * s + 8 * i + bk;
                    split2(p[0], p[1], bWh[(j * 4 + s) * 2 + i], bWl[(j * 4 + s) * 2 + i]);
                }
    } else {
        #pragma unroll
        for (int s = 0; s < 8; s++)
            #pragma unroll
            for (int i = 0; i < 2; i++) {
                const float* p = uw + (8 * sn + bq) * 128 + 16 * s + 8 * i + bk;
                split2(p[0], p[1], bWh[s * 2 + i], bWl[s * 2 + i]);
            }
    }

    // ---- Stage C (tensor, warps 0-5): Pg[48x48] = H(48x512) @ Hw^T ----
    const int arow  = lid & 15;
    const int ahalf = lid >> 4;
    if (wid < 6) {
        const int mtc = wid >> 1;
        const int nh  = wid & 1;
        float acc[3][4];
        #pragma unroll
        for (int j = 0; j < 3; j++)
            #pragma unroll
            for (int q = 0; q < 4; q++) acc[j][q] = 0.0f;

        #pragma unroll 4
        for (int s = 0; s < 32; s++) {
            int i = (16 * mtc + arow) * 8 + (s >> 2);
            int colA = ((s & 3) * 2 + ahalf) ^ ((i >> 3) & 7);
            uint32_t aaddr = smem_base + i * HS_STRIDE + (colA << 4);
            uint32_t ah[4], al[4];
            ldsm_x4(ah, aaddr);
            ldsm_x4(al, aaddr + 128);
            #pragma unroll
            for (int j = 0; j < 3; j++) {
                int hrow = 24 * nh + 8 * j + (lid & 7);
                int colB = (2 * s + ((lid >> 3) & 1)) ^ (hrow & 7);
                uint32_t baddr = smem_base + HWB + hrow * 2048 +
                                 ((lid >= 16) ? 1024 : 0) + (colB << 4);
                uint32_t bb[4];
                ldsm_x4(bb, baddr);
                mma_bf16(acc[j], ah, bb);
                mma_bf16(acc[j], ah, bb + 2);
                mma_bf16(acc[j], al, bb);
            }
        }
        #pragma unroll
        for (int j = 0; j < 3; j++) {
            int r = 16 * mtc + (lid >> 2);
            int c = 24 * nh + 8 * j + 2 * (lid & 3);
            *(float2*)&sm[S_PG + r * 48 + c]       = make_float2(acc[j][0], acc[j][1]);
            *(float2*)&sm[S_PG + (r + 8) * 48 + c] = make_float2(acc[j][2], acc[j][3]);
        }
    }
    __syncthreads();

    // ---- Stage D: elementwise affines + leaky ----
    for (int t = tid; t < Gn * Gn; t += TB) {
        float v = sm[S_PG + t];
        v = leaky(fmaf(v, pw1[t], pb1[t]));
        v = leaky(fmaf(v, pw2[t], pb2[t]));
        sm[S_PG + t] = v;
    }
    __syncthreads();

    // ---- Row softmax + row_weights (4 lanes per row) ----
    if (tid < 192) {
        int r = tid >> 2, q = tid & 3;
        const float* row = &sm[S_PG + r * 48 + q * 12];
        float m = -1e30f;
        #pragma unroll
        for (int h2 = 0; h2 < 12; h2++) m = fmaxf(m, row[h2]);
        m = fmaxf(m, __shfl_xor_sync(0xFFFFFFFF, m, 1));
        m = fmaxf(m, __shfl_xor_sync(0xFFFFFFFF, m, 2));
        float s = 0.0f;
        #pragma unroll
        for (int h2 = 0; h2 < 12; h2++) s += expf(row[h2] - m);
        s += __shfl_xor_sync(0xFFFFFFFF, s, 1);
        s += __shfl_xor_sync(0xFFFFFFFF, s, 2);
        float inv_s = 1.0f / s;
        float rw = 0.0f;
        #pragma unroll
        for (int h2 = 0; h2 < 12; h2++) {
            float p = expf(row[h2] - m) * inv_s;
            rw += 1.0f / (1.0f + p * p);
        }
        rw += __shfl_xor_sync(0xFFFFFFFF, rw, 1);
        rw += __shfl_xor_sync(0xFFFFFFFF, rw, 2);
        if (q == 0) sm[S_RW + r] = rw;
    }
    __syncthreads();

    // ---- scales ----
    if (tid < DIMn) {
        float acc = projb[tid];
        const float* pr = &projw[tid * Gn];
        #pragma unroll
        for (int g = 0; g < Gn; g++) acc = fmaf(sm[S_RW + g], pr[g], acc);
        sm[S_SC + tid] = acc;
    }
    __syncthreads();   // scales visible; Hw region free for z buffers

    // ---- Stage E: warp-specialized pipeline over 12 chunks of 32 rows ----
    // Producers (0-7): n16 strip, both m16 tiles. Consumers (8-15): n8 strip, both m16 tiles.
    for (int it = 0; it <= 12; it++) {
        if (eg == 0 && it < 12) {
            const int ch = it;
            const uint32_t zbB = ZB + (ch & 1) * Z_BUFSZ;
            #pragma unroll
            for (int mt2 = 0; mt2 < 2; mt2++) {
                const int R = ch * 32 + mt2 * 16;
                float d[2][4];
                #pragma unroll
                for (int j = 0; j < 2; j++)
                    #pragma unroll
                    for (int q = 0; q < 4; q++) d[j][q] = 0.0f;

                #pragma unroll
                for (int s = 0; s < 4; s++) {
                    int i = R + arow;
                    int colA = (2 * s + ahalf) ^ ((i >> 3) & 7);
                    uint32_t aaddr = smem_base + i * HS_STRIDE + (colA << 4);
                    uint32_t ah[4], al[4];
                    ldsm_x4(ah, aaddr);
                    ldsm_x4(al, aaddr + 128);
                    #pragma unroll
                    for (int j = 0; j < 2; j++) {
                        mma_bf16(d[j], ah, &bWh[(j * 4 + s) * 2]);
                        mma_bf16(d[j], ah, &bWl[(j * 4 + s) * 2]);
                        mma_bf16(d[j], al, &bWh[(j * 4 + s) * 2]);
                    }
                }

                const int zr = mt2 * 16 + bq;
                const float s0 = sm[S_SC + ch * 32 + zr];
                const float s1 = sm[S_SC + ch * 32 + zr + 8];
                #pragma unroll
                for (int j = 0; j < 2; j++) {
                    int n0 = 16 * sn + 8 * j + bk;
                    float v0 = leaky(fmaf(d[j][0], s0, sm[S_DB + n0]));
                    float v1 = leaky(fmaf(d[j][1], s0, sm[S_DB + n0 + 1]));
                    uint32_t h, l; split2(v0, v1, h, l);
                    *(uint32_t*)(smb + zbB + zr * Z_STRIDE + n0 * 2)       = h;
                    *(uint32_t*)(smb + zbB + zr * Z_STRIDE + 256 + n0 * 2) = l;
                    v0 = leaky(fmaf(d[j][2], s1, sm[S_DB + n0]));
                    v1 = leaky(fmaf(d[j][3], s1, sm[S_DB + n0 + 1]));
                    split2(v0, v1, h, l);
                    *(uint32_t*)(smb + zbB + (zr + 8) * Z_STRIDE + n0 * 2)       = h;
                    *(uint32_t*)(smb + zbB + (zr + 8) * Z_STRIDE + 256 + n0 * 2) = l;
                }
            }
        }
        if (eg == 1 && it >= 1) {
            const int ch = it - 1;
            const uint32_t zbS = smem_base + ZB + (ch & 1) * Z_BUFSZ;
            #pragma unroll
            for (int mt2 = 0; mt2 < 2; mt2++) {
                const int R = ch * 32 + mt2 * 16;
                float e2[4];
                #pragma unroll
                for (int q = 0; q < 4; q++) e2[q] = 0.0f;

                #pragma unroll
                for (int s = 0; s < 8; s++) {
                    uint32_t ah[4], al[4];
                    uint32_t za = zbS + (mt2 * 16 + arow) * Z_STRIDE + 32 * s + ahalf * 16;
                    ldsm_x4(ah, za);
                    ldsm_x4(al, za + 256);
                    mma_bf16(e2, ah, &bWh[s * 2]);
                    mma_bf16(e2, ah, &bWl[s * 2]);
                    mma_bf16(e2, al, &bWh[s * 2]);
                }

                int n0 = 8 * sn + bk;
                int r  = R + bq;
                float2 o;
                o.x = leaky(e2[0] + sm[S_UB + n0]);
                o.y = leaky(e2[1] + sm[S_UB + n0 + 1]);
                *(float2*)(out + ((size_t)(bidx * DIMn + r)) * 64 + n0) = o;
                o.x = leaky(e2[2] + sm[S_UB + n0]);
                o.y = leaky(e2[3] + sm[S_UB + n0 + 1]);
                *(float2*)(out + ((size_t)(bidx * DIMn + r + 8)) * 64 + n0) = o;
            }
        }
        __syncthreads();
    }
}

extern "C" void kernel_launch(void* const* d_in, const int* in_sizes, int n_in,
                              void* d_out, int out_size) {
    (void)in_sizes; (void)n_in; (void)out_size;
    const float* x      = (const float*)d_in[0];
    const float* W      = (const float*)d_in[1];
    const float* bia    = (const float*)d_in[2];
    const float* patchw = (const float*)d_in[3];
    const float* pw1    = (const float*)d_in[4];
    const float* pb1    = (const float*)d_in[5];
    const float* pw2    = (const float*)d_in[6];
    const float* pb2    = (const float*)d_in[7];
    const float* projw  = (const float*)d_in[8];
    const float* projb  = (const float*)d_in[9];
    const float* dw     = (const float*)d_in[10];
    const float* db     = (const float*)d_in[11];
    const float* uw     = (const float*)d_in[12];
    const float* ub     = (const float*)d_in[13];
    float* out = (float*)d_out;

    cudaFuncSetAttribute(autoreg_fused_kernel,
                         cudaFuncAttributeMaxDynamicSharedMemorySize,
                         SMEM_FLOATS * sizeof(float));
    autoreg_fused_kernel<<<Bn, TB, SMEM_FLOATS * sizeof(float)>>>(
        x, W, bia, patchw, pw1, pb1, pw2, pb2, projw, projb, dw, db, uw, ub, out);
}

// round 9
// speedup vs baseline: 1.8997x; 1.0543x over previous
#include <cuda_runtime.h>
#include <cuda_bf16.h>
#include <math.h>
#include <stdint.h>

#define TB 512

#define Bn   1024
#define DIMn 384
#define HIDn 64
#define Gn   48
#define MIDn 128

// ---------------- Shared-memory byte map ----------------
#define HS_STRIDE 272
#define HWB   104448
#define ZB    104448
#define Z_STRIDE 528
#define Z_BUFSZ 16896

#define S_PG  50688
#define S_X   52992
#define S_INV 53376
#define S_SW  53760
#define S_SC  53824
#define S_RW  54208
#define S_DB  54256
#define S_UB  54384
#define SMEM_FLOATS 54448   // 217792 bytes

// ---------------- mma.sync / ldmatrix helpers ----------------
__device__ __forceinline__ uint32_t smem_u32(const void* p) {
    uint32_t a;
    asm("{ .reg .u64 t; cvta.to.shared.u64 t, %1; cvt.u32.u64 %0, t; }" : "=r"(a) : "l"(p));
    return a;
}
__device__ __forceinline__ void mma_bf16(float* d, const uint32_t* a, const uint32_t* b) {
    asm volatile("mma.sync.aligned.m16n8k16.row.col.f32.bf16.bf16.f32 "
        "{%0,%1,%2,%3}, {%4,%5,%6,%7}, {%8,%9}, {%0,%1,%2,%3};"
        : "+f"(d[0]), "+f"(d[1]), "+f"(d[2]), "+f"(d[3])
        : "r"(a[0]), "r"(a[1]), "r"(a[2]), "r"(a[3]), "r"(b[0]), "r"(b[1]));
}
__device__ __forceinline__ void ldsm_x4(uint32_t* r, uint32_t addr) {
    asm volatile("ldmatrix.sync.aligned.m8n8.x4.shared.b16 {%0,%1,%2,%3}, [%4];"
        : "=r"(r[0]), "=r"(r[1]), "=r"(r[2]), "=r"(r[3]) : "r"(addr));
}

__device__ __forceinline__ float leaky(float v) { return (v >= 0.0f) ? v : 0.01f * v; }
__device__ __forceinline__ float gelu_exact(float v) {
    return 0.5f * v * (1.0f + erff(v * 0.70710678118654752f));
}
__device__ __forceinline__ uint32_t bf2(float a, float b) {
    __nv_bfloat162 t; t.x = __float2bfloat16(a); t.y = __float2bfloat16(b);
    return *reinterpret_cast<uint32_t*>(&t);
}
__device__ __forceinline__ void split2(float a, float b, uint32_t &hi, uint32_t &lo) {
    __nv_bfloat16 ha = __float2bfloat16(a);
    __nv_bfloat16 hb = __float2bfloat16(b);
    __nv_bfloat162 hp; hp.x = ha; hp.y = hb;
    hi = *reinterpret_cast<uint32_t*>(&hp);
    lo = bf2(a - __bfloat162float(ha), b - __bfloat162float(hb));
}
__device__ __forceinline__ uint32_t hs_addr(int i, int w) {
    int s = (i >> 3) & 7;
    return (uint32_t)(i * HS_STRIDE + ((((w >> 2) ^ s) << 4) | ((w & 3) << 2)));
}

__global__ void __launch_bounds__(TB, 1) autoreg_fused_kernel(
    const float* __restrict__ x,
    const float* __restrict__ W,
    const float* __restrict__ bia,
    const float* __restrict__ patchw,
    const float* __restrict__ pw1,
    const float* __restrict__ pb1,
    const float* __restrict__ pw2,
    const float* __restrict__ pb2,
    const float* __restrict__ projw,
    const float* __restrict__ projb,
    const float* __restrict__ dw,
    const float* __restrict__ db,
    const float* __restrict__ uw,
    const float* __restrict__ ub,
    float* __restrict__ out)
{
    extern __shared__ float sm[];
    char* smb = (char*)sm;
    const int tid  = threadIdx.x;
    const int wid  = tid >> 5;
    const int lid  = tid & 31;
    const int bidx = blockIdx.x;
    const uint32_t smem_base = smem_u32(sm);

    // ---- Load x row, bias vectors, raw patch weights ----
    for (int i = tid; i < DIMn; i += TB) {
        float xv = x[bidx * DIMn + i];
        sm[S_X + i]   = xv;
        sm[S_INV + i] = 1.0f / (fabsf(xv) + 1e-6f);
    }
    if (tid < MIDn) sm[S_DB + tid] = db[tid];
    if (tid >= 128 && tid < 192) sm[S_UB + tid - 128] = ub[tid - 128];
    if (tid >= 192 && tid < 256) sm[S_SW + tid - 192] = patchw[tid - 192];
    __syncthreads();

    // ---- Patch-weight softmax (thread 0; overlaps stage A) ----
    if (tid == 0) {
        float m = -1e30f;
        for (int i = 0; i < 64; i++) m = fmaxf(m, sm[S_SW + i]);
        float s = 0.0f;
        for (int i = 0; i < 64; i++) { float e = expf(sm[S_SW + i] - m); sm[S_SW + i] = e; s += e; }
        float is = 1.0f / s;
        for (int i = 0; i < 64; i++) sm[S_SW + i] *= is;
    }

    // ---- Stage A: H = gelu(x*W + inv*b), written as bf16 hi/lo split (float4 loads) ----
    for (int t = tid; t < 6144; t += TB) {
        int i = t >> 4, w4 = t & 15;
        float4 Wv = *(const float4*)(W + i * 64 + 4 * w4);
        float4 Bv = *(const float4*)(bia + i * 64 + 4 * w4);
        float xv = sm[S_X + i], iv = sm[S_INV + i];
        float v0 = gelu_exact(xv * Wv.x + iv * Bv.x);
        float v1 = gelu_exact(xv * Wv.y + iv * Bv.y);
        float v2 = gelu_exact(xv * Wv.z + iv * Bv.z);
        float v3 = gelu_exact(xv * Wv.w + iv * Bv.w);
        uint32_t h0, l0, h1, l1;
        split2(v0, v1, h0, l0);
        split2(v2, v3, h1, l1);
        uint32_t a = hs_addr(i, 2 * w4);
        *(uint2*)(smb + a)       = make_uint2(h0, h1);
        *(uint2*)(smb + a + 128) = make_uint2(l0, l1);
    }
    __syncthreads();

    // ---- Stage B: Hw ----
    for (int t = tid; t < 1536; t += TB) {
        int h = t >> 5, w = t & 31;
        float v0[8], v1[8];
        #pragma unroll
        for (int l = 0; l < 8; l++) {
            uint32_t a = hs_addr(h * 8 + l, w);
            uint32_t hw_ = *(uint32_t*)(smb + a);
            uint32_t lw_ = *(uint32_t*)(smb + a + 128);
            __nv_bfloat162 hb = *(__nv_bfloat162*)&hw_;
            __nv_bfloat162 lb = *(__nv_bfloat162*)&lw_;
            v0[l] = __bfloat162float(hb.x) + __bfloat162float(lb.x);
            v1[l] = __bfloat162float(hb.y) + __bfloat162float(lb.y);
        }
        int sh = h & 7;
        #pragma unroll
        for (int k = 0; k < 8; k++) {
            float a0 = 0.0f, a1 = 0.0f;
            #pragma unroll
            for (int l = 0; l < 8; l++) {
                float wv = sm[S_SW + k * 8 + l];
                a0 = fmaf(wv, v0[l], a0);
                a1 = fmaf(wv, v1[l], a1);
            }
            uint32_t hw2, lw2; split2(a0, a1, hw2, lw2);
            int W2 = k * 32 + w;
            uint32_t off = HWB + h * 2048 + ((((W2 >> 2) ^ sh) << 4) | ((W2 & 3) << 2));
            *(uint32_t*)(smb + off)        = hw2;
            *(uint32_t*)(smb + off + 1024) = lw2;
        }
    }
    __syncthreads();

    // ---- Gather loop-invariant weight B fragments (overlaps stage C) ----
    const int eg = wid >> 3;
    const int sn = wid & 7;
    const int bq = lid >> 2;
    const int bk = 2 * (lid & 3);

    uint32_t bWh[16], bWl[16];
    if (eg == 0) {
        #pragma unroll
        for (int j = 0; j < 2; j++)
            #pragma unroll
            for (int s = 0; s < 4; s++)
                #pragma unroll
                for (int i = 0; i < 2; i++) {
                    const float* p = dw + (16 * sn + 8 * j + bq) * 64 + 16 * s + 8 * i + bk;
                    split2(p[0], p[1], bWh[(j * 4 + s) * 2 + i], bWl[(j * 4 + s) * 2 + i]);
                }
    } else {
        #pragma unroll
        for (int s = 0; s < 8; s++)
            #pragma unroll
            for (int i = 0; i < 2; i++) {
                const float* p = uw + (8 * sn + bq) * 128 + 16 * s + 8 * i + bk;
                split2(p[0], p[1], bWh[s * 2 + i], bWl[s * 2 + i]);
            }
    }

    // ---- Stage C (tensor, warps 0-5): Pg[48x48] = H(48x512) @ Hw^T ----
    const int arow  = lid & 15;
    const int ahalf = lid >> 4;
    if (wid < 6) {
        const int mtc = wid >> 1;
        const int nh  = wid & 1;
        float acc[3][4];
        #pragma unroll
        for (int j = 0; j < 3; j++)
            #pragma unroll
            for (int q = 0; q < 4; q++) acc[j][q] = 0.0f;

        #pragma unroll 4
        for (int s = 0; s < 32; s++) {
            int i = (16 * mtc + arow) * 8 + (s >> 2);
            int colA = ((s & 3) * 2 + ahalf) ^ ((i >> 3) & 7);
            uint32_t aaddr = smem_base + i * HS_STRIDE + (colA << 4);
            uint32_t ah[4], al[4];
            ldsm_x4(ah, aaddr);
            ldsm_x4(al, aaddr + 128);
            #pragma unroll
            for (int j = 0; j < 3; j++) {
                int hrow = 24 * nh + 8 * j + (lid & 7);
                int colB = (2 * s + ((lid >> 3) & 1)) ^ (hrow & 7);
                uint32_t baddr = smem_base + HWB + hrow * 2048 +
                                 ((lid >= 16) ? 1024 : 0) + (colB << 4);
                uint32_t bb[4];
                ldsm_x4(bb, baddr);
                mma_bf16(acc[j], ah, bb);
                mma_bf16(acc[j], ah, bb + 2);
                mma_bf16(acc[j], al, bb);
            }
        }
        #pragma unroll
        for (int j = 0; j < 3; j++) {
            int r = 16 * mtc + (lid >> 2);
            int c = 24 * nh + 8 * j + 2 * (lid & 3);
            *(float2*)&sm[S_PG + r * 48 + c]       = make_float2(acc[j][0], acc[j][1]);
            *(float2*)&sm[S_PG + (r + 8) * 48 + c] = make_float2(acc[j][2], acc[j][3]);
        }
    }
    __syncthreads();

    // ---- Stage D: elementwise affines + leaky ----
    for (int t = tid; t < Gn * Gn; t += TB) {
        float v = sm[S_PG + t];
        v = leaky(fmaf(v, pw1[t], pb1[t]));
        v = leaky(fmaf(v, pw2[t], pb2[t]));
        sm[S_PG + t] = v;
    }
    __syncthreads();

    // ---- Row softmax + row_weights (4 lanes per row) ----
    if (tid < 192) {
        int r = tid >> 2, q = tid & 3;
        const float* row = &sm[S_PG + r * 48 + q * 12];
        float m = -1e30f;
        #pragma unroll
        for (int h2 = 0; h2 < 12; h2++) m = fmaxf(m, row[h2]);
        m = fmaxf(m, __shfl_xor_sync(0xFFFFFFFF, m, 1));
        m = fmaxf(m, __shfl_xor_sync(0xFFFFFFFF, m, 2));
        float s = 0.0f;
        #pragma unroll
        for (int h2 = 0; h2 < 12; h2++) s += expf(row[h2] - m);
        s += __shfl_xor_sync(0xFFFFFFFF, s, 1);
        s += __shfl_xor_sync(0xFFFFFFFF, s, 2);
        float inv_s = 1.0f / s;
        float rw = 0.0f;
        #pragma unroll
        for (int h2 = 0; h2 < 12; h2++) {
            float p = expf(row[h2] - m) * inv_s;
            rw += 1.0f / (1.0f + p * p);
        }
        rw += __shfl_xor_sync(0xFFFFFFFF, rw, 1);
        rw += __shfl_xor_sync(0xFFFFFFFF, rw, 2);
        if (q == 0) sm[S_RW + r] = rw;
    }
    __syncthreads();

    // ---- scales ----
    if (tid < DIMn) {
        float acc = projb[tid];
        const float* pr = &projw[tid * Gn];
        #pragma unroll
        for (int g = 0; g < Gn; g++) acc = fmaf(sm[S_RW + g], pr[g], acc);
        sm[S_SC + tid] = acc;
    }
    __syncthreads();   // scales visible; Hw region free for z buffers

    // ---- Stage E: warp-specialized pipeline, 12 chunks of 32 rows, 4 MMA chains/warp ----
    for (int it = 0; it <= 12; it++) {
        if (eg == 0 && it < 12) {
            const int ch = it;
            const uint32_t zbB = ZB + (ch & 1) * Z_BUFSZ;

            float d[2][2][4];
            #pragma unroll
            for (int m2 = 0; m2 < 2; m2++)
                #pragma unroll
                for (int j = 0; j < 2; j++)
                    #pragma unroll
                    for (int q = 0; q < 4; q++) d[m2][j][q] = 0.0f;

            #pragma unroll
            for (int s = 0; s < 4; s++) {
                #pragma unroll
                for (int m2 = 0; m2 < 2; m2++) {
                    int i = ch * 32 + m2 * 16 + arow;
                    int colA = (2 * s + ahalf) ^ ((i >> 3) & 7);
                    uint32_t aaddr = smem_base + i * HS_STRIDE + (colA << 4);
                    uint32_t ah[4], al[4];
                    ldsm_x4(ah, aaddr);
                    ldsm_x4(al, aaddr + 128);
                    #pragma unroll
                    for (int j = 0; j < 2; j++) {
                        mma_bf16(d[m2][j], ah, &bWh[(j * 4 + s) * 2]);
                        mma_bf16(d[m2][j], ah, &bWl[(j * 4 + s) * 2]);
                        mma_bf16(d[m2][j], al, &bWh[(j * 4 + s) * 2]);
                    }
                }
            }

            #pragma unroll
            for (int m2 = 0; m2 < 2; m2++) {
                const int zr = m2 * 16 + bq;
                const float s0 = sm[S_SC + ch * 32 + zr];
                const float s1 = sm[S_SC + ch * 32 + zr + 8];
                #pragma unroll
                for (int j = 0; j < 2; j++) {
                    int n0 = 16 * sn + 8 * j + bk;
                    float v0 = leaky(fmaf(d[m2][j][0], s0, sm[S_DB + n0]));
                    float v1 = leaky(fmaf(d[m2][j][1], s0, sm[S_DB + n0 + 1]));
                    uint32_t h, l; split2(v0, v1, h, l);
                    *(uint32_t*)(smb + zbB + zr * Z_STRIDE + n0 * 2)       = h;
                    *(uint32_t*)(smb + zbB + zr * Z_STRIDE + 256 + n0 * 2) = l;
                    v0 = leaky(fmaf(d[m2][j][2], s1, sm[S_DB + n0]));
                    v1 = leaky(fmaf(d[m2][j][3], s1, sm[S_DB + n0 + 1]));
                    split2(v0, v1, h, l);
                    *(uint32_t*)(smb + zbB + (zr + 8) * Z_STRIDE + n0 * 2)       = h;
                    *(uint32_t*)(smb + zbB + (zr + 8) * Z_STRIDE + 256 + n0 * 2) = l;
                }
            }
        }
        if (eg == 1 && it >= 1) {
            const int ch = it - 1;
            const uint32_t zbS = smem_base + ZB + (ch & 1) * Z_BUFSZ;

            float e[2][4], f[2][4];
            #pragma unroll
            for (int m2 = 0; m2 < 2; m2++)
                #pragma unroll
                for (int q = 0; q < 4; q++) { e[m2][q] = 0.0f; f[m2][q] = 0.0f; }

            #pragma unroll
            for (int s = 0; s < 8; s++) {
                #pragma unroll
                for (int m2 = 0; m2 < 2; m2++) {
                    uint32_t ah[4], al[4];
                    uint32_t za = zbS + (m2 * 16 + arow) * Z_STRIDE + 32 * s + ahalf * 16;
                    ldsm_x4(ah, za);
                    ldsm_x4(al, za + 256);
                    float* acc = (s & 1) ? f[m2] : e[m2];
                    mma_bf16(acc, ah, &bWh[s * 2]);
                    mma_bf16(acc, ah, &bWl[s * 2]);
                    mma_bf16(acc, al, &bWh[s * 2]);
                }
            }

            #pragma unroll
            for (int m2 = 0; m2 < 2; m2++) {
                const int R = ch * 32 + m2 * 16;
                int n0 = 8 * sn + bk;
                int r  = R + bq;
                float2 o;
                o.x = leaky(e[m2][0] + f[m2][0] + sm[S_UB + n0]);
                o.y = leaky(e[m2][1] + f[m2][1] + sm[S_UB + n0 + 1]);
                *(float2*)(out + ((size_t)(bidx * DIMn + r)) * 64 + n0) = o;
                o.x = leaky(e[m2][2] + f[m2][2] + sm[S_UB + n0]);
                o.y = leaky(e[m2][3] + f[m2][3] + sm[S_UB + n0 + 1]);
                *(float2*)(out + ((size_t)(bidx * DIMn + r + 8)) * 64 + n0) = o;
            }
        }
        __syncthreads();
    }
}

extern "C" void kernel_launch(void* const* d_in, const int* in_sizes, int n_in,
                              void* d_out, int out_size) {
    (void)in_sizes; (void)n_in; (void)out_size;
    const float* x      = (const float*)d_in[0];
    const float* W      = (const float*)d_in[1];
    const float* bia    = (const float*)d_in[2];
    const float* patchw = (const float*)d_in[3];
    const float* pw1    = (const float*)d_in[4];
    const float* pb1    = (const float*)d_in[5];
    const float* pw2    = (const float*)d_in[6];
    const float* pb2    = (const float*)d_in[7];
    const float* projw  = (const float*)d_in[8];
    const float* projb  = (const float*)d_in[9];
    const float* dw     = (const float*)d_in[10];
    const float* db     = (const float*)d_in[11];
    const float* uw     = (const float*)d_in[12];
    const float* ub     = (const float*)d_in[13];
    float* out = (float*)d_out;

    cudaFuncSetAttribute(autoreg_fused_kernel,
                         cudaFuncAttributeMaxDynamicSharedMemorySize,
                         SMEM_FLOATS * sizeof(float));
    autoreg_fused_kernel<<<Bn, TB, SMEM_FLOATS * sizeof(float)>>>(
        x, W, bia, patchw, pw1, pb1, pw2, pb2, projw, projb, dw, db, uw, ub, out);
}